// round 1
// baseline (speedup 1.0000x reference)
#include <cuda_runtime.h>
#include <cstdint>
#include <math.h>

#define B_  4
#define N_  2048
#define D_  512
#define H_  8
#define HD_ 64
#define E_  4
#define RD_ 2048
#define MT  (B_*N_)          // 8192 tokens

// ---------------- scratch (static device globals; no allocation) ----------------
__device__ float g_probs[MT*E_];
__device__ int   g_dtok[MT];
__device__ int   g_assigned[MT];
__device__ float g_rp[MT];
__device__ float g_h [MT*D_];
__device__ float g_q [MT*D_];
__device__ float g_k [MT*D_];
__device__ float g_v [MT*D_];
__device__ float g_o [MT*D_];
__device__ float g_z [MT*D_];
__device__ float g_hm[MT*D_];
__device__ float g_hid[MT*RD_];   // 64 MB

// ---------------- router: fp64 logits + softmax -> fp32 probs ----------------
__global__ void router_kernel(const float* __restrict__ x,
                              const float* __restrict__ rw,
                              const float* __restrict__ rb) {
    int warp = threadIdx.x >> 5;
    int lane = threadIdx.x & 31;
    int t = blockIdx.x * 8 + warp;
    const float* xr = x + t * D_;
    double a0 = 0, a1 = 0, a2 = 0, a3 = 0;
    for (int j = lane; j < D_; j += 32) {
        double xv = (double)xr[j];
        const float* w = rw + j * E_;
        a0 += xv * (double)w[0];
        a1 += xv * (double)w[1];
        a2 += xv * (double)w[2];
        a3 += xv * (double)w[3];
    }
    #pragma unroll
    for (int o = 16; o > 0; o >>= 1) {
        a0 += __shfl_down_sync(0xffffffffu, a0, o);
        a1 += __shfl_down_sync(0xffffffffu, a1, o);
        a2 += __shfl_down_sync(0xffffffffu, a2, o);
        a3 += __shfl_down_sync(0xffffffffu, a3, o);
    }
    if (lane == 0) {
        double l0 = a0 + (double)rb[0];
        double l1 = a1 + (double)rb[1];
        double l2 = a2 + (double)rb[2];
        double l3 = a3 + (double)rb[3];
        double mx = fmax(fmax(l0, l1), fmax(l2, l3));
        double e0 = exp(l0 - mx), e1 = exp(l1 - mx), e2 = exp(l2 - mx), e3 = exp(l3 - mx);
        double s = e0 + e1 + e2 + e3;
        float* p = g_probs + t * 4;
        p[0] = (float)(e0 / s);
        p[1] = (float)(e1 / s);
        p[2] = (float)(e2 / s);
        p[3] = (float)(e3 / s);
    }
}

// ---------------- expert-preferred assignment: bitonic top-k per batch ----------------
__device__ __forceinline__ unsigned int f2ord(float f) {
    unsigned int u = __float_as_uint(f);
    return (u & 0x80000000u) ? ~u : (u | 0x80000000u);
}

__global__ __launch_bounds__(1024) void assign_kernel() {
    const int b = blockIdx.x;
    const int tid = threadIdx.x;
    __shared__ unsigned long long key[N_];
    __shared__ int sas[N_];
    sas[tid] = -1; sas[tid + 1024] = -1;
    __syncthreads();

    const int capByE[4] = {1024, 512, 256, 256};

    for (int p = 0; p < 4; p++) {
        const int e = 3 - p;
        const int cap = capByE[e];
        // build keys: (ordered prob bits)<<32 | (~idx) ; assigned tokens sink with prob=-1
        #pragma unroll
        for (int ii = 0; ii < 2; ii++) {
            int i = tid + ii * 1024;
            float pr = (sas[i] < 0) ? g_probs[(b * N_ + i) * E_ + e] : -1.0f;
            unsigned int u = f2ord(pr);
            key[i] = ((unsigned long long)u << 32) | (unsigned int)(0xFFFFFFFFu - (unsigned)i);
        }
        __syncthreads();
        // bitonic sort, descending (largest key first)
        for (int k = 2; k <= N_; k <<= 1) {
            for (int j = k >> 1; j > 0; j >>= 1) {
                #pragma unroll
                for (int ii = 0; ii < 2; ii++) {
                    int i = tid + ii * 1024;
                    int ixj = i ^ j;
                    if (ixj > i) {
                        unsigned long long a = key[i], c = key[ixj];
                        bool desc = ((i & k) == 0);
                        bool sw = desc ? (a < c) : (a > c);
                        if (sw) { key[i] = c; key[ixj] = a; }
                    }
                }
                __syncthreads();
            }
        }
        // claim top-cap tokens for expert e
        #pragma unroll
        for (int ii = 0; ii < 2; ii++) {
            int pos = tid + ii * 1024;
            if (pos < cap) {
                unsigned long long kk = key[pos];
                if ((unsigned int)(kk >> 32) >= 0x80000000u) {  // a real (unassigned) prob
                    int tok = (int)(0xFFFFFFFFu - (unsigned int)(kk & 0xFFFFFFFFu));
                    sas[tok] = e;
                }
            }
        }
        __syncthreads();
    }
    // finalize
    #pragma unroll
    for (int ii = 0; ii < 2; ii++) {
        int i = tid + ii * 1024;
        int a = sas[i]; if (a < 0) a = 0;
        int gi = b * N_ + i;
        g_assigned[gi] = a;
        g_dtok[gi] = 64 << a;
        g_rp[gi] = g_probs[gi * E_ + a];
    }
}

// ---------------- layernorm + nested feature mask ----------------
template<int PASS>   // 0: x -> g_h (g1,b1);  1: g_z -> g_hm (g2,b2)
__global__ __launch_bounds__(256) void ln_kernel(const float* __restrict__ xin,
                                                 const float* __restrict__ gam,
                                                 const float* __restrict__ bet) {
    const int t = blockIdx.x;
    const float* r = (PASS == 0 ? xin : g_z) + t * D_;
    float* outp = (PASS == 0 ? g_h : g_hm) + t * D_;
    const int tid = threadIdx.x;
    const int lane = tid & 31, wid = tid >> 5;
    __shared__ float red[8];
    __shared__ float s_mu, s_rstd;

    float x0 = r[tid], x1 = r[tid + 256];
    float s = x0 + x1;
    #pragma unroll
    for (int o = 16; o > 0; o >>= 1) s += __shfl_down_sync(0xffffffffu, s, o);
    if (lane == 0) red[wid] = s;
    __syncthreads();
    if (tid == 0) {
        float tt = 0;
        #pragma unroll
        for (int w = 0; w < 8; w++) tt += red[w];
        s_mu = tt * (1.0f / 512.0f);
    }
    __syncthreads();
    float mu = s_mu;
    float d0 = x0 - mu, d1 = x1 - mu;
    float q = d0 * d0 + d1 * d1;
    #pragma unroll
    for (int o = 16; o > 0; o >>= 1) q += __shfl_down_sync(0xffffffffu, q, o);
    if (lane == 0) red[wid] = q;
    __syncthreads();
    if (tid == 0) {
        float tt = 0;
        #pragma unroll
        for (int w = 0; w < 8; w++) tt += red[w];
        s_rstd = rsqrtf(tt * (1.0f / 512.0f) + 1e-5f);
    }
    __syncthreads();
    float rstd = s_rstd;
    int dt = g_dtok[t];
    outp[tid]       = (tid < dt)       ? (d0 * rstd * gam[tid]       + bet[tid])       : 0.0f;
    outp[tid + 256] = (tid + 256 < dt) ? (d1 * rstd * gam[tid + 256] + bet[tid + 256]) : 0.0f;
}

// ---------------- fused SGEMM (128x128x8, 8x8 microtile) with epilogues ----------------
// EPI 0: g_h  @ w_qkv             -> mask, scatter to g_q/g_k/g_v [B,H,N,64]
// EPI 1: g_o  @ w_o  + b_o        -> mask, + x, -> g_z
// EPI 2: g_hm @ w1   + b1f        -> hidden mask, gelu, -> g_hid
// EPI 3: g_hid@ w2   + b2f        -> mask, g_z + (alpha*rp+1)*zp -> out
template<int EPI, int K, int NC>
__global__ __launch_bounds__(256) void gemm_kernel(const float* __restrict__ Bm,
                                                   const float* __restrict__ bias,
                                                   const float* __restrict__ resid,
                                                   const float* __restrict__ alpha,
                                                   float* __restrict__ outp) {
    const float* A = (EPI == 0) ? g_h : (EPI == 1) ? g_o : (EPI == 2) ? g_hm : g_hid;

    const int tid = threadIdx.x;
    const int tx = tid & 15, ty = tid >> 4;
    const int bx = blockIdx.x, by = blockIdx.y;

    __shared__ float As[8][128];
    __shared__ float Bs[8][128];

    float acc[8][8];
    #pragma unroll
    for (int i = 0; i < 8; i++)
        #pragma unroll
        for (int j = 0; j < 8; j++) acc[i][j] = 0.0f;

    const int mA = tid >> 1;
    const int kA = (tid & 1) * 4;
    const int kB = tid >> 5;
    const int nB = (tid & 31) * 4;
    const float* Aptr = A + (size_t)(by * 128 + mA) * K + kA;
    const float* Bptr = Bm + (size_t)kB * NC + bx * 128 + nB;

    for (int k0 = 0; k0 < K; k0 += 8) {
        float4 av = *(const float4*)(Aptr + k0);
        As[kA + 0][mA] = av.x; As[kA + 1][mA] = av.y;
        As[kA + 2][mA] = av.z; As[kA + 3][mA] = av.w;
        float4 bv = *(const float4*)(Bptr + (size_t)k0 * NC);
        *(float4*)&Bs[kB][nB] = bv;
        __syncthreads();
        #pragma unroll
        for (int kk = 0; kk < 8; kk++) {
            float a[8], bb[8];
            *(float4*)&a[0]  = *(const float4*)&As[kk][ty * 8];
            *(float4*)&a[4]  = *(const float4*)&As[kk][ty * 8 + 4];
            *(float4*)&bb[0] = *(const float4*)&Bs[kk][tx * 8];
            *(float4*)&bb[4] = *(const float4*)&Bs[kk][tx * 8 + 4];
            #pragma unroll
            for (int i = 0; i < 8; i++)
                #pragma unroll
                for (int j = 0; j < 8; j++) acc[i][j] += a[i] * bb[j];
        }
        __syncthreads();
    }

    const int mbase = by * 128 + ty * 8;
    const int nbase = bx * 128 + tx * 8;
    float aval = 0.0f;
    if (EPI == 3) aval = alpha[0];

    #pragma unroll
    for (int i = 0; i < 8; i++) {
        const int m = mbase + i;
        const int dt = g_dtok[m];
        #pragma unroll
        for (int j = 0; j < 8; j++) {
            const int n = nbase + j;
            float v = acc[i][j];
            if (EPI == 0) {
                int chunk = n >> 9, f = n & 511;
                float w = (f < dt) ? v : 0.0f;
                int head = f >> 6, d = f & 63;
                int bbp = m >> 11, tok = m & 2047;
                int idx = (((bbp * H_ + head) * N_ + tok) << 6) + d;
                if (chunk == 0) g_q[idx] = w;
                else if (chunk == 1) g_k[idx] = w;
                else g_v[idx] = w;
            } else if (EPI == 1) {
                float w = v + bias[n];
                w = (n < dt) ? w : 0.0f;
                g_z[m * D_ + n] = resid[m * D_ + n] + w;
            } else if (EPI == 2) {
                if (n < (dt << 2)) {
                    float w = v + bias[n];
                    float c = 0.7978845608028654f * (w + 0.044715f * w * w * w);
                    g_hid[m * RD_ + n] = 0.5f * w * (1.0f + tanhf(c));
                } else {
                    g_hid[m * RD_ + n] = 0.0f;
                }
            } else {  // EPI == 3
                float w = v + bias[n];
                float zp = (n < dt) ? w : 0.0f;
                outp[m * D_ + n] = g_z[m * D_ + n] + (aval * g_rp[m] + 1.0f) * zp;
            }
        }
    }
}

// ---------------- flash attention: Qtile 64 x Ktile 32, online softmax ----------------
__global__ __launch_bounds__(256) void attn_kernel() {
    const int bh = blockIdx.y;
    const int b = bh >> 3, h = bh & 7;
    const int q0 = blockIdx.x * 64;
    const int tid = threadIdx.x;
    const int tx = tid & 15, ty = tid >> 4;

    __shared__ float Qt[64][64];       // [d][r]  (transposed Q)
    __shared__ float Kp[64 * 33];      // Kt [d][c] stride-33; reused as Pt[32][65]
    __shared__ float Vs[32][64];       // [c][d]

    const float* qbase = g_q + ((size_t)(b * H_ + h) * N_ + q0) * HD_;
    const float* kbase = g_k + (size_t)(b * H_ + h) * N_ * HD_;
    const float* vbase = g_v + (size_t)(b * H_ + h) * N_ * HD_;

    for (int idx = tid; idx < 64 * 64; idx += 256) {
        int r = idx >> 6, d = idx & 63;
        Qt[d][r] = qbase[r * 64 + d];
    }

    float S[4][2];
    float O[4][4];
    float mrun[4], lrun[4];
    #pragma unroll
    for (int i = 0; i < 4; i++) {
        mrun[i] = -3.0e38f; lrun[i] = 0.0f;
        #pragma unroll
        for (int j = 0; j < 4; j++) O[i][j] = 0.0f;
    }
    const float scale = 0.125f;

    for (int k0 = 0; k0 < N_; k0 += 32) {
        for (int idx = tid; idx < 32 * 64; idx += 256) {
            int c = idx >> 6, d = idx & 63;
            float kv = kbase[(k0 + c) * 64 + d];
            Kp[d * 33 + c] = kv;
            Vs[c][d] = vbase[(k0 + c) * 64 + d];
        }
        __syncthreads();

        #pragma unroll
        for (int i = 0; i < 4; i++) { S[i][0] = 0.0f; S[i][1] = 0.0f; }
        #pragma unroll 4
        for (int d = 0; d < 64; d++) {
            float4 av = *(const float4*)&Qt[d][ty * 4];
            float b0 = Kp[d * 33 + tx * 2];
            float b1 = Kp[d * 33 + tx * 2 + 1];
            S[0][0] += av.x * b0; S[0][1] += av.x * b1;
            S[1][0] += av.y * b0; S[1][1] += av.y * b1;
            S[2][0] += av.z * b0; S[2][1] += av.z * b1;
            S[3][0] += av.w * b0; S[3][1] += av.w * b1;
        }
        __syncthreads();   // S done reading Kp; safe to overwrite with P^T

        #pragma unroll
        for (int i = 0; i < 4; i++) {
            float s0 = S[i][0] * scale, s1 = S[i][1] * scale;
            float mt = fmaxf(s0, s1);
            #pragma unroll
            for (int o = 1; o < 16; o <<= 1) mt = fmaxf(mt, __shfl_xor_sync(0xffffffffu, mt, o));
            float mnew = fmaxf(mrun[i], mt);
            float p0 = __expf(s0 - mnew), p1 = __expf(s1 - mnew);
            float ls = p0 + p1;
            #pragma unroll
            for (int o = 1; o < 16; o <<= 1) ls += __shfl_xor_sync(0xffffffffu, ls, o);
            float corr = __expf(mrun[i] - mnew);
            lrun[i] = lrun[i] * corr + ls;
            mrun[i] = mnew;
            O[i][0] *= corr; O[i][1] *= corr; O[i][2] *= corr; O[i][3] *= corr;
            Kp[(tx * 2 + 0) * 65 + ty * 4 + i] = p0;   // P^T
            Kp[(tx * 2 + 1) * 65 + ty * 4 + i] = p1;
        }
        __syncthreads();

        #pragma unroll 4
        for (int j = 0; j < 32; j++) {
            float a0 = Kp[j * 65 + ty * 4 + 0];
            float a1 = Kp[j * 65 + ty * 4 + 1];
            float a2 = Kp[j * 65 + ty * 4 + 2];
            float a3 = Kp[j * 65 + ty * 4 + 3];
            float4 bv = *(const float4*)&Vs[j][tx * 4];
            O[0][0] += a0 * bv.x; O[0][1] += a0 * bv.y; O[0][2] += a0 * bv.z; O[0][3] += a0 * bv.w;
            O[1][0] += a1 * bv.x; O[1][1] += a1 * bv.y; O[1][2] += a1 * bv.z; O[1][3] += a1 * bv.w;
            O[2][0] += a2 * bv.x; O[2][1] += a2 * bv.y; O[2][2] += a2 * bv.z; O[2][3] += a2 * bv.w;
            O[3][0] += a3 * bv.x; O[3][1] += a3 * bv.y; O[3][2] += a3 * bv.z; O[3][3] += a3 * bv.w;
        }
        __syncthreads();
    }

    #pragma unroll
    for (int i = 0; i < 4; i++) {
        int q = q0 + ty * 4 + i;
        int dtq = g_dtok[b * N_ + q];
        bool ok = (h << 6) < dtq;   // whole-head mask (dtok multiple of 64)
        float inv = 1.0f / lrun[i];
        float* dst = g_o + (size_t)(b * N_ + q) * D_ + (h << 6) + tx * 4;
        #pragma unroll
        for (int j = 0; j < 4; j++) dst[j] = ok ? O[i][j] * inv : 0.0f;
    }
}

// ---------------- auxiliary outputs (assigned, rp) if harness concatenates ----------------
__global__ void extras_kernel(float* __restrict__ outp, int write_rp) {
    int i = blockIdx.x * 256 + threadIdx.x;
    if (i < MT) {
        outp[MT * D_ + i] = (float)g_assigned[i];
        if (write_rp) outp[MT * D_ + MT + i] = g_rp[i];
    }
}

// ---------------- launch ----------------
extern "C" void kernel_launch(void* const* d_in, const int* in_sizes, int n_in,
                              void* d_out, int out_size) {
    const float* x     = (const float*)d_in[0];
    const float* r_w   = (const float*)d_in[1];
    const float* r_b   = (const float*)d_in[2];
    const float* g1    = (const float*)d_in[3];
    const float* b1    = (const float*)d_in[4];
    const float* g2    = (const float*)d_in[5];
    const float* b2    = (const float*)d_in[6];
    const float* w_qkv = (const float*)d_in[7];
    const float* w_o   = (const float*)d_in[8];
    const float* b_o   = (const float*)d_in[9];
    const float* w1    = (const float*)d_in[10];
    const float* b1f   = (const float*)d_in[11];
    const float* w2    = (const float*)d_in[12];
    const float* b2f   = (const float*)d_in[13];
    const float* alpha = (const float*)d_in[14];
    float* out = (float*)d_out;

    router_kernel<<<MT / 8, 256>>>(x, r_w, r_b);
    assign_kernel<<<B_, 1024>>>();
    ln_kernel<0><<<MT, 256>>>(x, g1, b1);
    gemm_kernel<0, 512, 1536><<<dim3(12, 64), 256>>>(w_qkv, nullptr, nullptr, nullptr, nullptr);
    attn_kernel<<<dim3(N_ / 64, B_ * H_), 256>>>();
    gemm_kernel<1, 512, 512><<<dim3(4, 64), 256>>>(w_o, b_o, x, nullptr, nullptr);
    ln_kernel<1><<<MT, 256>>>(x, g2, b2);
    gemm_kernel<2, 512, 2048><<<dim3(16, 64), 256>>>(w1, b1f, nullptr, nullptr, nullptr);
    gemm_kernel<3, 2048, 512><<<dim3(4, 64), 256>>>(w2, b2f, nullptr, alpha, out);

    if (out_size >= MT * D_ + MT) {
        int write_rp = (out_size >= MT * D_ + 2 * MT) ? 1 : 0;
        extras_kernel<<<(MT + 255) / 256, 256>>>(out, write_rp);
    }
}

// round 3
// speedup vs baseline: 1.4846x; 1.4846x over previous
#include <cuda_runtime.h>
#include <cuda_bf16.h>
#include <cstdint>
#include <math.h>

#define B_  4
#define N_  2048
#define D_  512
#define H_  8
#define HD_ 64
#define E_  4
#define MT  (B_*N_)          // 8192 tokens

// ---------------- scratch (static device globals; no allocation) ----------------
__device__ float g_probs[MT*E_];
__device__ int   g_dtok[MT];
__device__ int   g_assigned[MT];
__device__ float g_rp[MT];
__device__ float g_q [MT*D_];
__device__ float g_k [MT*D_];
__device__ float g_v [MT*D_];
__device__ float g_z [MT*D_];
// split-bf16 extended-K activations: A-ext layout = [hi | hi | lo] along K
__device__ __nv_bfloat16 g_h_ext  [MT*1536];
__device__ __nv_bfloat16 g_o_ext  [MT*1536];
__device__ __nv_bfloat16 g_hm_ext [MT*1536];
__device__ __nv_bfloat16 g_hid_ext[(size_t)MT*6144];
// split-bf16 extended-K weights: B-ext layout = [hi ; lo ; hi] along K rows
__device__ __nv_bfloat16 g_wqkv_ext[1536*1536];
__device__ __nv_bfloat16 g_wo_ext  [1536*512];
__device__ __nv_bfloat16 g_w1_ext  [1536*2048];
__device__ __nv_bfloat16 g_w2_ext  [6144*512];

__device__ __forceinline__ void bsplit(float v, __nv_bfloat16& h, __nv_bfloat16& l) {
    h = __float2bfloat16(v);
    l = __float2bfloat16(v - __bfloat162float(h));
}

// ---------------- router: fp64 logits + softmax -> fp32 probs ----------------
__global__ void router_kernel(const float* __restrict__ x,
                              const float* __restrict__ rw,
                              const float* __restrict__ rb) {
    int warp = threadIdx.x >> 5;
    int lane = threadIdx.x & 31;
    int t = blockIdx.x * 8 + warp;
    const float* xr = x + t * D_;
    double a0 = 0, a1 = 0, a2 = 0, a3 = 0;
    for (int j = lane; j < D_; j += 32) {
        double xv = (double)xr[j];
        const float* w = rw + j * E_;
        a0 += xv * (double)w[0];
        a1 += xv * (double)w[1];
        a2 += xv * (double)w[2];
        a3 += xv * (double)w[3];
    }
    #pragma unroll
    for (int o = 16; o > 0; o >>= 1) {
        a0 += __shfl_down_sync(0xffffffffu, a0, o);
        a1 += __shfl_down_sync(0xffffffffu, a1, o);
        a2 += __shfl_down_sync(0xffffffffu, a2, o);
        a3 += __shfl_down_sync(0xffffffffu, a3, o);
    }
    if (lane == 0) {
        double l0 = a0 + (double)rb[0];
        double l1 = a1 + (double)rb[1];
        double l2 = a2 + (double)rb[2];
        double l3 = a3 + (double)rb[3];
        double mx = fmax(fmax(l0, l1), fmax(l2, l3));
        double e0 = exp(l0 - mx), e1 = exp(l1 - mx), e2 = exp(l2 - mx), e3 = exp(l3 - mx);
        double s = e0 + e1 + e2 + e3;
        float* p = g_probs + t * 4;
        p[0] = (float)(e0 / s);
        p[1] = (float)(e1 / s);
        p[2] = (float)(e2 / s);
        p[3] = (float)(e3 / s);
    }
}

// ---------------- expert-preferred assignment: bitonic top-k per batch ----------------
__device__ __forceinline__ unsigned int f2ord(float f) {
    unsigned int u = __float_as_uint(f);
    return (u & 0x80000000u) ? ~u : (u | 0x80000000u);
}

__global__ __launch_bounds__(1024) void assign_kernel() {
    const int b = blockIdx.x;
    const int tid = threadIdx.x;
    __shared__ unsigned long long key[N_];
    __shared__ int sas[N_];
    sas[tid] = -1; sas[tid + 1024] = -1;
    __syncthreads();

    const int capByE[4] = {1024, 512, 256, 256};

    for (int p = 0; p < 4; p++) {
        const int e = 3 - p;
        const int cap = capByE[e];
        #pragma unroll
        for (int ii = 0; ii < 2; ii++) {
            int i = tid + ii * 1024;
            float pr = (sas[i] < 0) ? g_probs[(b * N_ + i) * E_ + e] : -1.0f;
            unsigned int u = f2ord(pr);
            key[i] = ((unsigned long long)u << 32) | (unsigned int)(0xFFFFFFFFu - (unsigned)i);
        }
        __syncthreads();
        for (int k = 2; k <= N_; k <<= 1) {
            for (int j = k >> 1; j > 0; j >>= 1) {
                #pragma unroll
                for (int ii = 0; ii < 2; ii++) {
                    int i = tid + ii * 1024;
                    int ixj = i ^ j;
                    if (ixj > i) {
                        unsigned long long a = key[i], c = key[ixj];
                        bool desc = ((i & k) == 0);
                        bool sw = desc ? (a < c) : (a > c);
                        if (sw) { key[i] = c; key[ixj] = a; }
                    }
                }
                __syncthreads();
            }
        }
        #pragma unroll
        for (int ii = 0; ii < 2; ii++) {
            int pos = tid + ii * 1024;
            if (pos < cap) {
                unsigned long long kk = key[pos];
                if ((unsigned int)(kk >> 32) >= 0x80000000u) {
                    int tok = (int)(0xFFFFFFFFu - (unsigned int)(kk & 0xFFFFFFFFu));
                    sas[tok] = e;
                }
            }
        }
        __syncthreads();
    }
    #pragma unroll
    for (int ii = 0; ii < 2; ii++) {
        int i = tid + ii * 1024;
        int a = sas[i]; if (a < 0) a = 0;
        int gi = b * N_ + i;
        g_assigned[gi] = a;
        g_dtok[gi] = 64 << a;
        g_rp[gi] = g_probs[gi * E_ + a];
    }
}

// ---------------- layernorm + mask -> split-bf16 A-ext ----------------
template<int PASS>   // 0: x -> g_h_ext (g1,b1);  1: g_z -> g_hm_ext (g2,b2)
__global__ __launch_bounds__(256) void ln_kernel(const float* __restrict__ xin,
                                                 const float* __restrict__ gam,
                                                 const float* __restrict__ bet) {
    const int t = blockIdx.x;
    const float* r = (PASS == 0 ? xin : g_z) + t * D_;
    const int tid = threadIdx.x;
    const int lane = tid & 31, wid = tid >> 5;
    __shared__ float red[8];
    __shared__ float s_mu, s_rstd;

    float x0 = r[tid], x1 = r[tid + 256];
    float s = x0 + x1;
    #pragma unroll
    for (int o = 16; o > 0; o >>= 1) s += __shfl_down_sync(0xffffffffu, s, o);
    if (lane == 0) red[wid] = s;
    __syncthreads();
    if (tid == 0) {
        float tt = 0;
        #pragma unroll
        for (int w = 0; w < 8; w++) tt += red[w];
        s_mu = tt * (1.0f / 512.0f);
    }
    __syncthreads();
    float mu = s_mu;
    float d0 = x0 - mu, d1 = x1 - mu;
    float q = d0 * d0 + d1 * d1;
    #pragma unroll
    for (int o = 16; o > 0; o >>= 1) q += __shfl_down_sync(0xffffffffu, q, o);
    if (lane == 0) red[wid] = q;
    __syncthreads();
    if (tid == 0) {
        float tt = 0;
        #pragma unroll
        for (int w = 0; w < 8; w++) tt += red[w];
        s_rstd = rsqrtf(tt * (1.0f / 512.0f) + 1e-5f);
    }
    __syncthreads();
    float rstd = s_rstd;
    int dt = g_dtok[t];
    float y0 = (tid < dt)       ? (d0 * rstd * gam[tid]       + bet[tid])       : 0.0f;
    float y1 = (tid + 256 < dt) ? (d1 * rstd * gam[tid + 256] + bet[tid + 256]) : 0.0f;
    __nv_bfloat16 h0, l0, h1, l1;
    bsplit(y0, h0, l0); bsplit(y1, h1, l1);
    __nv_bfloat16* e = (PASS == 0 ? g_h_ext : g_hm_ext) + (size_t)t * 1536;
    e[tid]        = h0; e[tid + 512]        = h0; e[tid + 1024]        = l0;
    e[tid + 256]  = h1; e[tid + 256 + 512]  = h1; e[tid + 256 + 1024]  = l1;
}

// ---------------- weight conversion fp32 [K,N] -> B-ext bf16 [3K,N] = [hi;lo;hi] ----------------
template<int W>
__global__ void wconv_kernel(const float* __restrict__ Wsrc, int total) {
    __nv_bfloat16* ext = (W == 0) ? g_wqkv_ext : (W == 1) ? g_wo_ext : (W == 2) ? g_w1_ext : g_w2_ext;
    int i = blockIdx.x * 256 + threadIdx.x;
    if (i >= total) return;
    __nv_bfloat16 h, l;
    bsplit(Wsrc[i], h, l);
    ext[i] = h; ext[total + i] = l; ext[2 * total + i] = h;
}

// ---------------- tensor-core GEMM (bf16 split via extended K) ----------------
// CTA 128x128, k-slab 32, double-buffered cp.async, ldmatrix + mma.m16n8k16
// EPI 0: h_ext  @ wqkv_ext        -> mask, scatter to g_q/g_k/g_v [B,H,N,64]
// EPI 1: o_ext  @ wo_ext  + b_o   -> mask, + x, -> g_z
// EPI 2: hm_ext @ w1_ext  + b1f   -> hidden mask, gelu, -> g_hid_ext (A-ext)
// EPI 3: hid_ext@ w2_ext  + b2f   -> mask, g_z + (alpha*rp+1)*zp -> out

__device__ __forceinline__ void mma16816(float* c, const uint32_t* a, const uint32_t* b) {
    asm volatile("mma.sync.aligned.m16n8k16.row.col.f32.bf16.bf16.f32 "
                 "{%0,%1,%2,%3},{%4,%5,%6,%7},{%8,%9},{%0,%1,%2,%3};"
                 : "+f"(c[0]), "+f"(c[1]), "+f"(c[2]), "+f"(c[3])
                 : "r"(a[0]), "r"(a[1]), "r"(a[2]), "r"(a[3]), "r"(b[0]), "r"(b[1]));
}

template<int K3, int NC>
__device__ __forceinline__ void stage_load(const __nv_bfloat16* __restrict__ Ag,
                                           const __nv_bfloat16* __restrict__ Bg,
                                           unsigned char* As, unsigned char* Bs,
                                           int slab, int tid) {
    // A tile: 128 rows x 32 halves (64B rows), swizzle chunk ^ ((r>>1)&3)
    #pragma unroll
    for (int i = 0; i < 2; i++) {
        int id = tid + i * 256;
        int r = id >> 2, c = id & 3;
        const __nv_bfloat16* g = Ag + (size_t)r * K3 + slab * 32 + c * 8;
        uint32_t s = (uint32_t)__cvta_generic_to_shared(As + r * 64 + ((c ^ ((r >> 1) & 3)) << 4));
        asm volatile("cp.async.cg.shared.global [%0],[%1],16;\n" :: "r"(s), "l"(g));
    }
    // B tile: 32 rows x 128 halves (256B rows), swizzle chunk ^ (r&7)
    #pragma unroll
    for (int i = 0; i < 2; i++) {
        int id = tid + i * 256;
        int r = id >> 4, c = id & 15;
        const __nv_bfloat16* g = Bg + (size_t)(slab * 32 + r) * NC + c * 8;
        uint32_t s = (uint32_t)__cvta_generic_to_shared(Bs + r * 256 + ((c ^ (r & 7)) << 4));
        asm volatile("cp.async.cg.shared.global [%0],[%1],16;\n" :: "r"(s), "l"(g));
    }
    asm volatile("cp.async.commit_group;\n");
}

template<int EPI, int K3, int NC>
__global__ void __launch_bounds__(256, 2) tgemm_kernel(const float* __restrict__ bias,
                                                       const float* __restrict__ resid,
                                                       const float* __restrict__ alpha,
                                                       float* __restrict__ outp) {
    const __nv_bfloat16* Aext = (EPI == 0) ? g_h_ext : (EPI == 1) ? g_o_ext
                              : (EPI == 2) ? g_hm_ext : g_hid_ext;
    const __nv_bfloat16* Bext = (EPI == 0) ? g_wqkv_ext : (EPI == 1) ? g_wo_ext
                              : (EPI == 2) ? g_w1_ext : g_w2_ext;

    __shared__ __align__(16) unsigned char smA[2][128 * 64];
    __shared__ __align__(16) unsigned char smB[2][32 * 256];

    const int tid = threadIdx.x, lane = tid & 31, wid = tid >> 5;
    const int bm = blockIdx.y * 128, bn = blockIdx.x * 128;
    const int wm = (wid >> 2) * 64;
    const int widn = wid & 3;           // warp n-slot (32 cols each)

    const __nv_bfloat16* Ag = Aext + (size_t)bm * K3;
    const __nv_bfloat16* Bg = Bext + bn;

    float acc[4][4][4];
    #pragma unroll
    for (int i = 0; i < 4; i++)
        #pragma unroll
        for (int j = 0; j < 4; j++)
            #pragma unroll
            for (int k = 0; k < 4; k++) acc[i][j][k] = 0.0f;

    constexpr int NS = K3 / 32;
    stage_load<K3, NC>(Ag, Bg, smA[0], smB[0], 0, tid);

    #pragma unroll 1
    for (int s = 0; s < NS; s++) {
        int cur = s & 1;
        if (s + 1 < NS) {
            stage_load<K3, NC>(Ag, Bg, smA[cur ^ 1], smB[cur ^ 1], s + 1, tid);
            asm volatile("cp.async.wait_group 1;\n");
        } else {
            asm volatile("cp.async.wait_group 0;\n");
        }
        __syncthreads();

        unsigned char* As = smA[cur];
        unsigned char* Bs = smB[cur];
        #pragma unroll
        for (int kk = 0; kk < 2; kk++) {
            uint32_t af[4][4], bfr[4][2];
            #pragma unroll
            for (int mi = 0; mi < 4; mi++) {
                int r = wm + mi * 16 + (lane & 7) + ((lane & 8) ? 8 : 0);
                int c = kk * 2 + ((lane & 16) ? 1 : 0);
                uint32_t sa = (uint32_t)__cvta_generic_to_shared(
                    As + r * 64 + ((c ^ ((r >> 1) & 3)) << 4));
                asm volatile("ldmatrix.sync.aligned.m8n8.x4.shared.b16 {%0,%1,%2,%3},[%4];"
                             : "=r"(af[mi][0]), "=r"(af[mi][1]), "=r"(af[mi][2]), "=r"(af[mi][3])
                             : "r"(sa));
            }
            #pragma unroll
            for (int np = 0; np < 2; np++) {
                int kr = kk * 16 + (lane & 7) + ((lane & 8) ? 8 : 0);
                int c = widn * 4 + np * 2 + ((lane & 16) ? 1 : 0);
                uint32_t sb = (uint32_t)__cvta_generic_to_shared(
                    Bs + kr * 256 + ((c ^ (kr & 7)) << 4));
                asm volatile("ldmatrix.sync.aligned.m8n8.x4.trans.shared.b16 {%0,%1,%2,%3},[%4];"
                             : "=r"(bfr[np * 2][0]), "=r"(bfr[np * 2][1]),
                               "=r"(bfr[np * 2 + 1][0]), "=r"(bfr[np * 2 + 1][1])
                             : "r"(sb));
            }
            #pragma unroll
            for (int mi = 0; mi < 4; mi++)
                #pragma unroll
                for (int ni = 0; ni < 4; ni++)
                    mma16816(acc[mi][ni], af[mi], bfr[ni]);
        }
        __syncthreads();
    }

    // ---------------- epilogue ----------------
    const int l4 = lane >> 2, l2 = (lane & 3) * 2;
    float aval = 0.0f;
    if (EPI == 3) aval = alpha[0];

    #pragma unroll
    for (int mi = 0; mi < 4; mi++) {
        #pragma unroll
        for (int hh = 0; hh < 2; hh++) {
            int m = bm + wm + mi * 16 + l4 + hh * 8;
            int dt = g_dtok[m];
            #pragma unroll
            for (int ni = 0; ni < 4; ni++) {
                int n = bn + widn * 32 + ni * 8 + l2;
                float v0 = acc[mi][ni][hh * 2 + 0];
                float v1 = acc[mi][ni][hh * 2 + 1];
                if (EPI == 0) {
                    int chunk = n >> 9, f = n & 511;
                    int head = f >> 6, d = f & 63, bb = m >> 11, tok = m & 2047;
                    size_t idx = ((size_t)((bb * H_ + head) * N_ + tok)) * 64 + d;
                    float2 val;
                    val.x = (f < dt) ? v0 : 0.0f;
                    val.y = (f + 1 < dt) ? v1 : 0.0f;
                    if (chunk == 0)      *(float2*)(g_q + idx) = val;
                    else if (chunk == 1) *(float2*)(g_k + idx) = val;
                    else                 *(float2*)(g_v + idx) = val;
                } else if (EPI == 1) {
                    float w0 = v0 + bias[n];
                    float w1 = v1 + bias[n + 1];
                    if (n >= dt) w0 = 0.0f;
                    if (n + 1 >= dt) w1 = 0.0f;
                    const float2 xr = *(const float2*)(resid + (size_t)m * 512 + n);
                    float2 o; o.x = xr.x + w0; o.y = xr.y + w1;
                    *(float2*)(g_z + (size_t)m * 512 + n) = o;
                } else if (EPI == 2) {
                    int dh = dt << 2;
                    float h0 = 0.0f, h1 = 0.0f;
                    if (n < dh) {
                        float w = v0 + bias[n];
                        float c = 0.7978845608028654f * (w + 0.044715f * w * w * w);
                        h0 = 0.5f * w * (1.0f + tanhf(c));
                    }
                    if (n + 1 < dh) {
                        float w = v1 + bias[n + 1];
                        float c = 0.7978845608028654f * (w + 0.044715f * w * w * w);
                        h1 = 0.5f * w * (1.0f + tanhf(c));
                    }
                    __nv_bfloat16 a0, b0, a1, b1;
                    bsplit(h0, a0, b0); bsplit(h1, a1, b1);
                    __nv_bfloat162 hi; hi.x = a0; hi.y = a1;
                    __nv_bfloat162 lo; lo.x = b0; lo.y = b1;
                    size_t base = (size_t)m * 6144 + n;
                    *(__nv_bfloat162*)(g_hid_ext + base)        = hi;
                    *(__nv_bfloat162*)(g_hid_ext + base + 2048) = hi;
                    *(__nv_bfloat162*)(g_hid_ext + base + 4096) = lo;
                } else {  // EPI == 3
                    float w0 = v0 + bias[n];
                    float w1 = v1 + bias[n + 1];
                    float zp0 = (n < dt) ? w0 : 0.0f;
                    float zp1 = (n + 1 < dt) ? w1 : 0.0f;
                    float gm = aval * g_rp[m] + 1.0f;
                    const float2 zz = *(const float2*)(g_z + (size_t)m * 512 + n);
                    float2 o; o.x = zz.x + gm * zp0; o.y = zz.y + gm * zp1;
                    *(float2*)(outp + (size_t)m * 512 + n) = o;
                }
            }
        }
    }
}

// ---------------- flash attention: Qtile 64 x Ktile 32, online softmax (SIMT fp32) ----------------
__global__ __launch_bounds__(256) void attn_kernel() {
    const int bh = blockIdx.y;
    const int b = bh >> 3, h = bh & 7;
    const int q0 = blockIdx.x * 64;
    const int tid = threadIdx.x;
    const int tx = tid & 15, ty = tid >> 4;

    __shared__ float Qt[64][64];
    __shared__ float Kp[64 * 33];
    __shared__ float Vs[32][64];

    const float* qbase = g_q + ((size_t)(b * H_ + h) * N_ + q0) * HD_;
    const float* kbase = g_k + (size_t)(b * H_ + h) * N_ * HD_;
    const float* vbase = g_v + (size_t)(b * H_ + h) * N_ * HD_;

    for (int idx = tid; idx < 64 * 64; idx += 256) {
        int r = idx >> 6, d = idx & 63;
        Qt[d][r] = qbase[r * 64 + d];
    }

    float S[4][2];
    float O[4][4];
    float mrun[4], lrun[4];
    #pragma unroll
    for (int i = 0; i < 4; i++) {
        mrun[i] = -3.0e38f; lrun[i] = 0.0f;
        #pragma unroll
        for (int j = 0; j < 4; j++) O[i][j] = 0.0f;
    }
    const float scale = 0.125f;

    for (int k0 = 0; k0 < N_; k0 += 32) {
        for (int idx = tid; idx < 32 * 64; idx += 256) {
            int c = idx >> 6, d = idx & 63;
            float kv = kbase[(k0 + c) * 64 + d];
            Kp[d * 33 + c] = kv;
            Vs[c][d] = vbase[(k0 + c) * 64 + d];
        }
        __syncthreads();

        #pragma unroll
        for (int i = 0; i < 4; i++) { S[i][0] = 0.0f; S[i][1] = 0.0f; }
        #pragma unroll 4
        for (int d = 0; d < 64; d++) {
            float4 av = *(const float4*)&Qt[d][ty * 4];
            float b0 = Kp[d * 33 + tx * 2];
            float b1 = Kp[d * 33 + tx * 2 + 1];
            S[0][0] += av.x * b0; S[0][1] += av.x * b1;
            S[1][0] += av.y * b0; S[1][1] += av.y * b1;
            S[2][0] += av.z * b0; S[2][1] += av.z * b1;
            S[3][0] += av.w * b0; S[3][1] += av.w * b1;
        }
        __syncthreads();

        #pragma unroll
        for (int i = 0; i < 4; i++) {
            float s0 = S[i][0] * scale, s1 = S[i][1] * scale;
            float mt = fmaxf(s0, s1);
            #pragma unroll
            for (int o = 1; o < 16; o <<= 1) mt = fmaxf(mt, __shfl_xor_sync(0xffffffffu, mt, o));
            float mnew = fmaxf(mrun[i], mt);
            float p0 = __expf(s0 - mnew), p1 = __expf(s1 - mnew);
            float ls = p0 + p1;
            #pragma unroll
            for (int o = 1; o < 16; o <<= 1) ls += __shfl_xor_sync(0xffffffffu, ls, o);
            float corr = __expf(mrun[i] - mnew);
            lrun[i] = lrun[i] * corr + ls;
            mrun[i] = mnew;
            O[i][0] *= corr; O[i][1] *= corr; O[i][2] *= corr; O[i][3] *= corr;
            Kp[(tx * 2 + 0) * 65 + ty * 4 + i] = p0;
            Kp[(tx * 2 + 1) * 65 + ty * 4 + i] = p1;
        }
        __syncthreads();

        #pragma unroll 4
        for (int j = 0; j < 32; j++) {
            float a0 = Kp[j * 65 + ty * 4 + 0];
            float a1 = Kp[j * 65 + ty * 4 + 1];
            float a2 = Kp[j * 65 + ty * 4 + 2];
            float a3 = Kp[j * 65 + ty * 4 + 3];
            float4 bv = *(const float4*)&Vs[j][tx * 4];
            O[0][0] += a0 * bv.x; O[0][1] += a0 * bv.y; O[0][2] += a0 * bv.z; O[0][3] += a0 * bv.w;
            O[1][0] += a1 * bv.x; O[1][1] += a1 * bv.y; O[1][2] += a1 * bv.z; O[1][3] += a1 * bv.w;
            O[2][0] += a2 * bv.x; O[2][1] += a2 * bv.y; O[2][2] += a2 * bv.z; O[2][3] += a2 * bv.w;
            O[3][0] += a3 * bv.x; O[3][1] += a3 * bv.y; O[3][2] += a3 * bv.z; O[3][3] += a3 * bv.w;
        }
        __syncthreads();
    }

    #pragma unroll
    for (int i = 0; i < 4; i++) {
        int q = q0 + ty * 4 + i;
        int m = b * N_ + q;
        int dtq = g_dtok[m];
        bool ok = (h << 6) < dtq;
        float inv = 1.0f / lrun[i];
        __nv_bfloat16* e = g_o_ext + (size_t)m * 1536 + (h << 6) + tx * 4;
        #pragma unroll
        for (int j = 0; j < 4; j++) {
            float w = ok ? O[i][j] * inv : 0.0f;
            __nv_bfloat16 hh, ll;
            bsplit(w, hh, ll);
            e[j] = hh; e[j + 512] = hh; e[j + 1024] = ll;
        }
    }
}

// ---------------- auxiliary outputs (assigned, rp) if harness concatenates ----------------
__global__ void extras_kernel(float* __restrict__ outp, int write_rp) {
    int i = blockIdx.x * 256 + threadIdx.x;
    if (i < MT) {
        outp[MT * D_ + i] = (float)g_assigned[i];
        if (write_rp) outp[MT * D_ + MT + i] = g_rp[i];
    }
}

// ---------------- launch ----------------
extern "C" void kernel_launch(void* const* d_in, const int* in_sizes, int n_in,
                              void* d_out, int out_size) {
    const float* x     = (const float*)d_in[0];
    const float* r_w   = (const float*)d_in[1];
    const float* r_b   = (const float*)d_in[2];
    const float* g1    = (const float*)d_in[3];
    const float* b1    = (const float*)d_in[4];
    const float* g2    = (const float*)d_in[5];
    const float* b2    = (const float*)d_in[6];
    const float* w_qkv = (const float*)d_in[7];
    const float* w_o   = (const float*)d_in[8];
    const float* b_o   = (const float*)d_in[9];
    const float* w1    = (const float*)d_in[10];
    const float* b1f   = (const float*)d_in[11];
    const float* w2    = (const float*)d_in[12];
    const float* b2f   = (const float*)d_in[13];
    const float* alpha = (const float*)d_in[14];
    float* out = (float*)d_out;

    router_kernel<<<MT / 8, 256>>>(x, r_w, r_b);
    assign_kernel<<<B_, 1024>>>();

    wconv_kernel<0><<<(512 * 1536 + 255) / 256, 256>>>(w_qkv, 512 * 1536);
    wconv_kernel<1><<<(512 * 512 + 255) / 256, 256>>>(w_o, 512 * 512);
    wconv_kernel<2><<<(512 * 2048 + 255) / 256, 256>>>(w1, 512 * 2048);
    wconv_kernel<3><<<(2048 * 512 + 255) / 256, 256>>>(w2, 2048 * 512);

    ln_kernel<0><<<MT, 256>>>(x, g1, b1);
    tgemm_kernel<0, 1536, 1536><<<dim3(12, 64), 256>>>(nullptr, nullptr, nullptr, nullptr);
    attn_kernel<<<dim3(N_ / 64, B_ * H_), 256>>>();
    tgemm_kernel<1, 1536, 512><<<dim3(4, 64), 256>>>(b_o, x, nullptr, nullptr);
    ln_kernel<1><<<MT, 256>>>(x, g2, b2);
    tgemm_kernel<2, 1536, 2048><<<dim3(16, 64), 256>>>(b1f, nullptr, nullptr, nullptr);
    tgemm_kernel<3, 6144, 512><<<dim3(4, 64), 256>>>(b2f, nullptr, alpha, out);

    if (out_size >= MT * D_ + MT) {
        int write_rp = (out_size >= MT * D_ + 2 * MT) ? 1 : 0;
        extras_kernel<<<(MT + 255) / 256, 256>>>(out, write_rp);
    }
}

// round 5
// speedup vs baseline: 3.2017x; 2.1566x over previous
#include <cuda_runtime.h>
#include <cuda_bf16.h>
#include <cstdint>
#include <math.h>

#define B_  4
#define N_  2048
#define D_  512
#define H_  8
#define HD_ 64
#define E_  4
#define MT  (B_*N_)          // 8192 tokens

// ---------------- scratch (static device globals; no allocation) ----------------
__device__ float g_probs[MT*E_];
__device__ int   g_dtok[MT];
__device__ int   g_assigned[MT];
__device__ int   g_perm[MT];          // per batch: tokens sorted by expert desc (e3,e2,e1,e0)
__device__ float g_rp[MT];
__device__ float g_z [MT*D_];
// split-bf16 extended-K activations: A-ext layout = [hi | hi | lo] along K
__device__ __nv_bfloat16 g_h_ext  [MT*1536];
__device__ __nv_bfloat16 g_o_ext  [MT*1536];
__device__ __nv_bfloat16 g_hm_ext [MT*1536];
__device__ __nv_bfloat16 g_hid_ext[(size_t)MT*6144];
// attention operands (per b,h planes)
__device__ __nv_bfloat16 g_qext[(size_t)B_*H_*N_*192];   // [hi|hi|lo] along d
__device__ __nv_bfloat16 g_kext[(size_t)B_*H_*N_*192];   // [hi|lo|hi] along d
__device__ __nv_bfloat16 g_vh [(size_t)B_*H_*N_*64];
__device__ __nv_bfloat16 g_vl [(size_t)B_*H_*N_*64];
// split-bf16 extended-K weights: B-ext layout = [hi ; lo ; hi] along K rows
__device__ __nv_bfloat16 g_wqkv_ext[1536*1536];
__device__ __nv_bfloat16 g_wo_ext  [1536*512];
__device__ __nv_bfloat16 g_w1_ext  [1536*2048];
__device__ __nv_bfloat16 g_w2_ext  [6144*512];

// fattn block table: 80 chunks/batch: head h gets C_h/64 chunks
__constant__ int c_head[80] = {
    0,0,0,0,0,0,0,0,0,0,0,0,0,0,0,0,0,0,0,0,0,0,0,0,0,0,0,0,0,0,0,0,
    1,1,1,1,1,1,1,1,1,1,1,1,1,1,1,1,
    2,2,2,2,2,2,2,2, 3,3,3,3,3,3,3,3,
    4,4,4,4, 5,5,5,5, 6,6,6,6, 7,7,7,7};
__constant__ int c_chunk[80] = {
    0,1,2,3,4,5,6,7,8,9,10,11,12,13,14,15,16,17,18,19,20,21,22,23,24,25,26,27,28,29,30,31,
    0,1,2,3,4,5,6,7,8,9,10,11,12,13,14,15,
    0,1,2,3,4,5,6,7, 0,1,2,3,4,5,6,7,
    0,1,2,3, 0,1,2,3, 0,1,2,3, 0,1,2,3};

__device__ __forceinline__ void bsplit(float v, __nv_bfloat16& h, __nv_bfloat16& l) {
    h = __float2bfloat16(v);
    l = __float2bfloat16(v - __bfloat162float(h));
}
__device__ __forceinline__ uint32_t packb(__nv_bfloat16 a, __nv_bfloat16 b) {
    __nv_bfloat162 t; t.x = a; t.y = b; return *(uint32_t*)&t;
}

// ---------------- router: fp64 logits + softmax -> fp32 probs ----------------
__global__ void router_kernel(const float* __restrict__ x,
                              const float* __restrict__ rw,
                              const float* __restrict__ rb) {
    int warp = threadIdx.x >> 5;
    int lane = threadIdx.x & 31;
    int t = blockIdx.x * 8 + warp;
    const float* xr = x + t * D_;
    double a0 = 0, a1 = 0, a2 = 0, a3 = 0;
    for (int j = lane; j < D_; j += 32) {
        double xv = (double)xr[j];
        const float* w = rw + j * E_;
        a0 += xv * (double)w[0];
        a1 += xv * (double)w[1];
        a2 += xv * (double)w[2];
        a3 += xv * (double)w[3];
    }
    #pragma unroll
    for (int o = 16; o > 0; o >>= 1) {
        a0 += __shfl_down_sync(0xffffffffu, a0, o);
        a1 += __shfl_down_sync(0xffffffffu, a1, o);
        a2 += __shfl_down_sync(0xffffffffu, a2, o);
        a3 += __shfl_down_sync(0xffffffffu, a3, o);
    }
    if (lane == 0) {
        double l0 = a0 + (double)rb[0];
        double l1 = a1 + (double)rb[1];
        double l2 = a2 + (double)rb[2];
        double l3 = a3 + (double)rb[3];
        double mx = fmax(fmax(l0, l1), fmax(l2, l3));
        double e0 = exp(l0 - mx), e1 = exp(l1 - mx), e2 = exp(l2 - mx), e3 = exp(l3 - mx);
        double s = e0 + e1 + e2 + e3;
        float* p = g_probs + t * 4;
        p[0] = (float)(e0 / s);
        p[1] = (float)(e1 / s);
        p[2] = (float)(e2 / s);
        p[3] = (float)(e3 / s);
    }
}

// ---------------- expert-preferred assignment + perm ----------------
__device__ __forceinline__ unsigned int f2ord(float f) {
    unsigned int u = __float_as_uint(f);
    return (u & 0x80000000u) ? ~u : (u | 0x80000000u);
}

__global__ __launch_bounds__(1024) void assign_kernel() {
    const int b = blockIdx.x;
    const int tid = threadIdx.x;
    __shared__ unsigned long long key[N_];
    __shared__ int sas[N_];
    __shared__ int cnt[4];
    sas[tid] = -1; sas[tid + 1024] = -1;
    if (tid < 4) cnt[tid] = 0;
    __syncthreads();

    const int capByE[4] = {1024, 512, 256, 256};

    for (int p = 0; p < 4; p++) {
        const int e = 3 - p;
        const int cap = capByE[e];
        #pragma unroll
        for (int ii = 0; ii < 2; ii++) {
            int i = tid + ii * 1024;
            float pr = (sas[i] < 0) ? g_probs[(b * N_ + i) * E_ + e] : -1.0f;
            unsigned int u = f2ord(pr);
            key[i] = ((unsigned long long)u << 32) | (unsigned int)(0xFFFFFFFFu - (unsigned)i);
        }
        __syncthreads();
        for (int k = 2; k <= N_; k <<= 1) {
            for (int j = k >> 1; j > 0; j >>= 1) {
                #pragma unroll
                for (int ii = 0; ii < 2; ii++) {
                    int i = tid + ii * 1024;
                    int ixj = i ^ j;
                    if (ixj > i) {
                        unsigned long long a = key[i], c = key[ixj];
                        bool desc = ((i & k) == 0);
                        bool sw = desc ? (a < c) : (a > c);
                        if (sw) { key[i] = c; key[ixj] = a; }
                    }
                }
                __syncthreads();
            }
        }
        #pragma unroll
        for (int ii = 0; ii < 2; ii++) {
            int pos = tid + ii * 1024;
            if (pos < cap) {
                unsigned long long kk = key[pos];
                if ((unsigned int)(kk >> 32) >= 0x80000000u) {
                    int tokv = (int)(0xFFFFFFFFu - (unsigned int)(kk & 0xFFFFFFFFu));
                    sas[tokv] = e;
                }
            }
        }
        __syncthreads();
    }
    const int startE[4] = {1024, 512, 256, 0};   // e0..e3 segment starts in perm
    #pragma unroll
    for (int ii = 0; ii < 2; ii++) {
        int i = tid + ii * 1024;
        int a = sas[i]; if (a < 0) a = 0;
        int gi = b * N_ + i;
        g_assigned[gi] = a;
        g_dtok[gi] = 64 << a;
        g_rp[gi] = g_probs[gi * E_ + a];
        int pos = startE[a] + atomicAdd(&cnt[a], 1);
        g_perm[b * N_ + pos] = i;
    }
}

// ---------------- zero-fill inactive (token, col) slices of o_ext ----------------
__global__ void zfill_kernel() {
    int m = blockIdx.x;
    int c = threadIdx.x * 2;
    int dt = g_dtok[m];
    if (c >= dt) {
        __nv_bfloat162 z; z.x = __float2bfloat16(0.0f); z.y = z.x;
        size_t base = (size_t)m * 1536 + c;
        *(__nv_bfloat162*)(g_o_ext + base)        = z;
        *(__nv_bfloat162*)(g_o_ext + base + 512)  = z;
        *(__nv_bfloat162*)(g_o_ext + base + 1024) = z;
    }
}

// ---------------- layernorm + mask -> split-bf16 A-ext ----------------
template<int PASS>   // 0: x -> g_h_ext (g1,b1);  1: g_z -> g_hm_ext (g2,b2)
__global__ __launch_bounds__(256) void ln_kernel(const float* __restrict__ xin,
                                                 const float* __restrict__ gam,
                                                 const float* __restrict__ bet) {
    const int t = blockIdx.x;
    const float* r = (PASS == 0 ? xin : g_z) + t * D_;
    const int tid = threadIdx.x;
    const int lane = tid & 31, wid = tid >> 5;
    __shared__ float red[8];
    __shared__ float s_mu, s_rstd;

    float x0 = r[tid], x1 = r[tid + 256];
    float s = x0 + x1;
    #pragma unroll
    for (int o = 16; o > 0; o >>= 1) s += __shfl_down_sync(0xffffffffu, s, o);
    if (lane == 0) red[wid] = s;
    __syncthreads();
    if (tid == 0) {
        float tt = 0;
        #pragma unroll
        for (int w = 0; w < 8; w++) tt += red[w];
        s_mu = tt * (1.0f / 512.0f);
    }
    __syncthreads();
    float mu = s_mu;
    float d0 = x0 - mu, d1 = x1 - mu;
    float q = d0 * d0 + d1 * d1;
    #pragma unroll
    for (int o = 16; o > 0; o >>= 1) q += __shfl_down_sync(0xffffffffu, q, o);
    if (lane == 0) red[wid] = q;
    __syncthreads();
    if (tid == 0) {
        float tt = 0;
        #pragma unroll
        for (int w = 0; w < 8; w++) tt += red[w];
        s_rstd = rsqrtf(tt * (1.0f / 512.0f) + 1e-5f);
    }
    __syncthreads();
    float rstd = s_rstd;
    int dt = g_dtok[t];
    float y0 = (tid < dt)       ? (d0 * rstd * gam[tid]       + bet[tid])       : 0.0f;
    float y1 = (tid + 256 < dt) ? (d1 * rstd * gam[tid + 256] + bet[tid + 256]) : 0.0f;
    __nv_bfloat16 h0, l0, h1, l1;
    bsplit(y0, h0, l0); bsplit(y1, h1, l1);
    __nv_bfloat16* e = (PASS == 0 ? g_h_ext : g_hm_ext) + (size_t)t * 1536;
    e[tid]        = h0; e[tid + 512]        = h0; e[tid + 1024]        = l0;
    e[tid + 256]  = h1; e[tid + 256 + 512]  = h1; e[tid + 256 + 1024]  = l1;
}

// ---------------- weight conversion fp32 [K,N] -> B-ext bf16 [3K,N] = [hi;lo;hi] ----------------
template<int W>
__global__ void wconv_kernel(const float* __restrict__ Wsrc, int total) {
    __nv_bfloat16* ext = (W == 0) ? g_wqkv_ext : (W == 1) ? g_wo_ext : (W == 2) ? g_w1_ext : g_w2_ext;
    int i = blockIdx.x * 256 + threadIdx.x;
    if (i >= total) return;
    __nv_bfloat16 h, l;
    bsplit(Wsrc[i], h, l);
    ext[i] = h; ext[total + i] = l; ext[2 * total + i] = h;
}

// ---------------- tensor-core GEMM (bf16 split via extended K) ----------------
__device__ __forceinline__ void mma16816(float* c, const uint32_t* a, const uint32_t* b) {
    asm volatile("mma.sync.aligned.m16n8k16.row.col.f32.bf16.bf16.f32 "
                 "{%0,%1,%2,%3},{%4,%5,%6,%7},{%8,%9},{%0,%1,%2,%3};"
                 : "+f"(c[0]), "+f"(c[1]), "+f"(c[2]), "+f"(c[3])
                 : "r"(a[0]), "r"(a[1]), "r"(a[2]), "r"(a[3]), "r"(b[0]), "r"(b[1]));
}

template<int K3, int NC>
__device__ __forceinline__ void stage_load(const __nv_bfloat16* __restrict__ Ag,
                                           const __nv_bfloat16* __restrict__ Bg,
                                           unsigned char* As, unsigned char* Bs,
                                           int slab, int tid) {
    #pragma unroll
    for (int i = 0; i < 2; i++) {
        int id = tid + i * 256;
        int r = id >> 2, c = id & 3;
        const __nv_bfloat16* g = Ag + (size_t)r * K3 + slab * 32 + c * 8;
        uint32_t s = (uint32_t)__cvta_generic_to_shared(As + r * 64 + ((c ^ ((r >> 1) & 3)) << 4));
        asm volatile("cp.async.cg.shared.global [%0],[%1],16;\n" :: "r"(s), "l"(g));
    }
    #pragma unroll
    for (int i = 0; i < 2; i++) {
        int id = tid + i * 256;
        int r = id >> 4, c = id & 15;
        const __nv_bfloat16* g = Bg + (size_t)(slab * 32 + r) * NC + c * 8;
        uint32_t s = (uint32_t)__cvta_generic_to_shared(Bs + r * 256 + ((c ^ (r & 7)) << 4));
        asm volatile("cp.async.cg.shared.global [%0],[%1],16;\n" :: "r"(s), "l"(g));
    }
    asm volatile("cp.async.commit_group;\n");
}

template<int EPI, int K3, int NC>
__global__ void __launch_bounds__(256, 2) tgemm_kernel(const float* __restrict__ bias,
                                                       const float* __restrict__ resid,
                                                       const float* __restrict__ alpha,
                                                       float* __restrict__ outp) {
    const __nv_bfloat16* Aext = (EPI == 0) ? g_h_ext : (EPI == 1) ? g_o_ext
                              : (EPI == 2) ? g_hm_ext : g_hid_ext;
    const __nv_bfloat16* Bext = (EPI == 0) ? g_wqkv_ext : (EPI == 1) ? g_wo_ext
                              : (EPI == 2) ? g_w1_ext : g_w2_ext;

    __shared__ __align__(16) unsigned char smA[2][128 * 64];
    __shared__ __align__(16) unsigned char smB[2][32 * 256];

    const int tid = threadIdx.x, lane = tid & 31, wid = tid >> 5;
    const int bm = blockIdx.y * 128, bn = blockIdx.x * 128;
    const int wm = (wid >> 2) * 64;
    const int widn = wid & 3;

    const __nv_bfloat16* Ag = Aext + (size_t)bm * K3;
    const __nv_bfloat16* Bg = Bext + bn;

    float acc[4][4][4];
    #pragma unroll
    for (int i = 0; i < 4; i++)
        #pragma unroll
        for (int j = 0; j < 4; j++)
            #pragma unroll
            for (int k = 0; k < 4; k++) acc[i][j][k] = 0.0f;

    constexpr int NS = K3 / 32;
    stage_load<K3, NC>(Ag, Bg, smA[0], smB[0], 0, tid);

    #pragma unroll 1
    for (int s = 0; s < NS; s++) {
        int cur = s & 1;
        if (s + 1 < NS) {
            stage_load<K3, NC>(Ag, Bg, smA[cur ^ 1], smB[cur ^ 1], s + 1, tid);
            asm volatile("cp.async.wait_group 1;\n");
        } else {
            asm volatile("cp.async.wait_group 0;\n");
        }
        __syncthreads();

        unsigned char* As = smA[cur];
        unsigned char* Bs = smB[cur];
        #pragma unroll
        for (int kk = 0; kk < 2; kk++) {
            uint32_t af[4][4], bfr[4][2];
            #pragma unroll
            for (int mi = 0; mi < 4; mi++) {
                int r = wm + mi * 16 + (lane & 7) + ((lane & 8) ? 8 : 0);
                int c = kk * 2 + ((lane & 16) ? 1 : 0);
                uint32_t sa = (uint32_t)__cvta_generic_to_shared(
                    As + r * 64 + ((c ^ ((r >> 1) & 3)) << 4));
                asm volatile("ldmatrix.sync.aligned.m8n8.x4.shared.b16 {%0,%1,%2,%3},[%4];"
                             : "=r"(af[mi][0]), "=r"(af[mi][1]), "=r"(af[mi][2]), "=r"(af[mi][3])
                             : "r"(sa));
            }
            #pragma unroll
            for (int np = 0; np < 2; np++) {
                int kr = kk * 16 + (lane & 7) + ((lane & 8) ? 8 : 0);
                int c = widn * 4 + np * 2 + ((lane & 16) ? 1 : 0);
                uint32_t sb = (uint32_t)__cvta_generic_to_shared(
                    Bs + kr * 256 + ((c ^ (kr & 7)) << 4));
                asm volatile("ldmatrix.sync.aligned.m8n8.x4.trans.shared.b16 {%0,%1,%2,%3},[%4];"
                             : "=r"(bfr[np * 2][0]), "=r"(bfr[np * 2][1]),
                               "=r"(bfr[np * 2 + 1][0]), "=r"(bfr[np * 2 + 1][1])
                             : "r"(sb));
            }
            #pragma unroll
            for (int mi = 0; mi < 4; mi++)
                #pragma unroll
                for (int ni = 0; ni < 4; ni++)
                    mma16816(acc[mi][ni], af[mi], bfr[ni]);
        }
        __syncthreads();
    }

    const int l4 = lane >> 2, l2 = (lane & 3) * 2;
    float aval = 0.0f;
    if (EPI == 3) aval = alpha[0];

    #pragma unroll
    for (int mi = 0; mi < 4; mi++) {
        #pragma unroll
        for (int hh = 0; hh < 2; hh++) {
            int m = bm + wm + mi * 16 + l4 + hh * 8;
            int dt = g_dtok[m];
            #pragma unroll
            for (int ni = 0; ni < 4; ni++) {
                int n = bn + widn * 32 + ni * 8 + l2;
                float v0 = acc[mi][ni][hh * 2 + 0];
                float v1 = acc[mi][ni][hh * 2 + 1];
                if (EPI == 0) {
                    int chunk = n >> 9, f = n & 511;
                    int head = f >> 6, d = f & 63, bb = m >> 11, tokv = m & 2047;
                    bool on = (f < dt);
                    float w0 = on ? v0 : 0.0f;
                    float w1 = on ? v1 : 0.0f;
                    __nv_bfloat16 hh0, ll0, hh1, ll1;
                    bsplit(w0, hh0, ll0); bsplit(w1, hh1, ll1);
                    __nv_bfloat162 hi2; hi2.x = hh0; hi2.y = hh1;
                    __nv_bfloat162 lo2; lo2.x = ll0; lo2.y = ll1;
                    size_t base = (size_t)((bb * H_ + head) * N_ + tokv);
                    if (chunk == 0) {
                        __nv_bfloat16* p = g_qext + base * 192 + d;
                        *(__nv_bfloat162*)(p)       = hi2;
                        *(__nv_bfloat162*)(p + 64)  = hi2;
                        *(__nv_bfloat162*)(p + 128) = lo2;
                    } else if (chunk == 1) {
                        __nv_bfloat16* p = g_kext + base * 192 + d;
                        *(__nv_bfloat162*)(p)       = hi2;
                        *(__nv_bfloat162*)(p + 64)  = lo2;
                        *(__nv_bfloat162*)(p + 128) = hi2;
                    } else {
                        *(__nv_bfloat162*)(g_vh + base * 64 + d) = hi2;
                        *(__nv_bfloat162*)(g_vl + base * 64 + d) = lo2;
                    }
                } else if (EPI == 1) {
                    float w0 = v0 + bias[n];
                    float w1 = v1 + bias[n + 1];
                    if (n >= dt) w0 = 0.0f;
                    if (n + 1 >= dt) w1 = 0.0f;
                    const float2 xr = *(const float2*)(resid + (size_t)m * 512 + n);
                    float2 o; o.x = xr.x + w0; o.y = xr.y + w1;
                    *(float2*)(g_z + (size_t)m * 512 + n) = o;
                } else if (EPI == 2) {
                    int dh = dt << 2;
                    float h0 = 0.0f, h1 = 0.0f;
                    if (n < dh) {
                        float w = v0 + bias[n];
                        float c = 0.7978845608028654f * (w + 0.044715f * w * w * w);
                        h0 = 0.5f * w * (1.0f + tanhf(c));
                    }
                    if (n + 1 < dh) {
                        float w = v1 + bias[n + 1];
                        float c = 0.7978845608028654f * (w + 0.044715f * w * w * w);
                        h1 = 0.5f * w * (1.0f + tanhf(c));
                    }
                    __nv_bfloat16 a0, b0, a1, b1;
                    bsplit(h0, a0, b0); bsplit(h1, a1, b1);
                    __nv_bfloat162 hi; hi.x = a0; hi.y = a1;
                    __nv_bfloat162 lo; lo.x = b0; lo.y = b1;
                    size_t base = (size_t)m * 6144 + n;
                    *(__nv_bfloat162*)(g_hid_ext + base)        = hi;
                    *(__nv_bfloat162*)(g_hid_ext + base + 2048) = hi;
                    *(__nv_bfloat162*)(g_hid_ext + base + 4096) = lo;
                } else {
                    float w0 = v0 + bias[n];
                    float w1 = v1 + bias[n + 1];
                    float zp0 = (n < dt) ? w0 : 0.0f;
                    float zp1 = (n + 1 < dt) ? w1 : 0.0f;
                    float gm = aval * g_rp[m] + 1.0f;
                    const float2 zz = *(const float2*)(g_z + (size_t)m * 512 + n);
                    float2 o; o.x = zz.x + gm * zp0; o.y = zz.y + gm * zp1;
                    *(float2*)(outp + (size_t)m * 512 + n) = o;
                }
            }
        }
    }
}

// ---------------- tensor-core flash attention, active-row gather ----------------
// block: 64 active q rows (one head), 4 warps x m16, key tiles of 64
// smem: Q_ext 64x400B, K_ext 64x400B, Vh 64x144B, Vl 64x144B = 69632 B
__global__ void __launch_bounds__(128, 3) fattn_kernel() {
    const int b = blockIdx.y;
    const int slot = blockIdx.x;
    const int h = c_head[slot];
    const int ch = c_chunk[slot];

    extern __shared__ __align__(16) unsigned char sm[];
    unsigned char* Qs  = sm;
    unsigned char* Ks  = sm + 64 * 400;
    unsigned char* Vhs = sm + 2 * 64 * 400;
    unsigned char* Vls = Vhs + 64 * 144;
    __shared__ int tok[64];

    const int tid = threadIdx.x, lane = tid & 31, wid = tid >> 5;

    if (tid < 64) tok[tid] = g_perm[b * N_ + ch * 64 + tid];
    __syncthreads();

    const size_t bh = (size_t)(b * H_ + h) * N_;

    // gather Q_ext rows
    for (int i = tid; i < 64 * 24; i += 128) {
        int r = i / 24, c = i % 24;
        const __nv_bfloat16* g = g_qext + (bh + tok[r]) * 192 + c * 8;
        uint32_t s = (uint32_t)__cvta_generic_to_shared(Qs + r * 400 + c * 16);
        asm volatile("cp.async.cg.shared.global [%0],[%1],16;\n" :: "r"(s), "l"(g));
    }
    asm volatile("cp.async.commit_group;\ncp.async.wait_group 0;\n");
    __syncthreads();

    float accO[8][4];
    #pragma unroll
    for (int i = 0; i < 8; i++)
        #pragma unroll
        for (int j = 0; j < 4; j++) accO[i][j] = 0.0f;
    float m0 = -3.0e38f, m1 = -3.0e38f, l0 = 0.0f, l1 = 0.0f;

    for (int k0 = 0; k0 < N_; k0 += 64) {
        // load K_ext + V tiles
        for (int i = tid; i < 64 * 24; i += 128) {
            int r = i / 24, c = i % 24;
            const __nv_bfloat16* g = g_kext + (bh + k0 + r) * 192 + c * 8;
            uint32_t s = (uint32_t)__cvta_generic_to_shared(Ks + r * 400 + c * 16);
            asm volatile("cp.async.cg.shared.global [%0],[%1],16;\n" :: "r"(s), "l"(g));
        }
        for (int i = tid; i < 64 * 8; i += 128) {
            int r = i / 8, c = i % 8;
            const __nv_bfloat16* gh = g_vh + (bh + k0 + r) * 64 + c * 8;
            const __nv_bfloat16* gl = g_vl + (bh + k0 + r) * 64 + c * 8;
            uint32_t sh = (uint32_t)__cvta_generic_to_shared(Vhs + r * 144 + c * 16);
            uint32_t sl = (uint32_t)__cvta_generic_to_shared(Vls + r * 144 + c * 16);
            asm volatile("cp.async.cg.shared.global [%0],[%1],16;\n" :: "r"(sh), "l"(gh));
            asm volatile("cp.async.cg.shared.global [%0],[%1],16;\n" :: "r"(sl), "l"(gl));
        }
        asm volatile("cp.async.commit_group;\ncp.async.wait_group 0;\n");
        __syncthreads();

        // S = Q K^T over ext K=192
        float S[8][4];
        #pragma unroll
        for (int i = 0; i < 8; i++)
            #pragma unroll
            for (int j = 0; j < 4; j++) S[i][j] = 0.0f;

        const int qrow = wid * 16 + (lane & 15);
        const int krow7 = (lane & 7) + ((lane & 16) ? 8 : 0);
        const int kcsel = ((lane & 8) ? 1 : 0);
        #pragma unroll
        for (int ks = 0; ks < 12; ks++) {
            uint32_t qf[4];
            uint32_t sa = (uint32_t)__cvta_generic_to_shared(
                Qs + qrow * 400 + (ks * 2 + (lane >> 4)) * 16);
            asm volatile("ldmatrix.sync.aligned.m8n8.x4.shared.b16 {%0,%1,%2,%3},[%4];"
                         : "=r"(qf[0]), "=r"(qf[1]), "=r"(qf[2]), "=r"(qf[3]) : "r"(sa));
            #pragma unroll
            for (int p = 0; p < 4; p++) {
                uint32_t kf[4];
                uint32_t sb = (uint32_t)__cvta_generic_to_shared(
                    Ks + (p * 16 + krow7) * 400 + (ks * 2 + kcsel) * 16);
                asm volatile("ldmatrix.sync.aligned.m8n8.x4.shared.b16 {%0,%1,%2,%3},[%4];"
                             : "=r"(kf[0]), "=r"(kf[1]), "=r"(kf[2]), "=r"(kf[3]) : "r"(sb));
                mma16816(S[2 * p],     qf, kf);
                mma16816(S[2 * p + 1], qf, kf + 2);
            }
        }

        // online softmax (rows: lo = l/4, hi = l/4+8)
        float mx0 = -3.0e38f, mx1 = -3.0e38f;
        #pragma unroll
        for (int ni = 0; ni < 8; ni++) {
            S[ni][0] *= 0.125f; S[ni][1] *= 0.125f; S[ni][2] *= 0.125f; S[ni][3] *= 0.125f;
            mx0 = fmaxf(mx0, fmaxf(S[ni][0], S[ni][1]));
            mx1 = fmaxf(mx1, fmaxf(S[ni][2], S[ni][3]));
        }
        mx0 = fmaxf(mx0, __shfl_xor_sync(0xffffffffu, mx0, 1));
        mx0 = fmaxf(mx0, __shfl_xor_sync(0xffffffffu, mx0, 2));
        mx1 = fmaxf(mx1, __shfl_xor_sync(0xffffffffu, mx1, 1));
        mx1 = fmaxf(mx1, __shfl_xor_sync(0xffffffffu, mx1, 2));
        float mn0 = fmaxf(m0, mx0), mn1 = fmaxf(m1, mx1);
        float cr0 = __expf(m0 - mn0), cr1 = __expf(m1 - mn1);
        float s0 = 0.0f, s1 = 0.0f;
        uint32_t pha[8], phb[8], pla[8], plb[8];
        #pragma unroll
        for (int ni = 0; ni < 8; ni++) {
            float p00 = __expf(S[ni][0] - mn0), p01 = __expf(S[ni][1] - mn0);
            float p10 = __expf(S[ni][2] - mn1), p11 = __expf(S[ni][3] - mn1);
            s0 += p00 + p01; s1 += p10 + p11;
            __nv_bfloat16 h00, l00, h01, l01, h10, l10, h11, l11;
            bsplit(p00, h00, l00); bsplit(p01, h01, l01);
            bsplit(p10, h10, l10); bsplit(p11, h11, l11);
            pha[ni] = packb(h00, h01); phb[ni] = packb(h10, h11);
            pla[ni] = packb(l00, l01); plb[ni] = packb(l10, l11);
        }
        s0 += __shfl_xor_sync(0xffffffffu, s0, 1);
        s0 += __shfl_xor_sync(0xffffffffu, s0, 2);
        s1 += __shfl_xor_sync(0xffffffffu, s1, 1);
        s1 += __shfl_xor_sync(0xffffffffu, s1, 2);
        l0 = l0 * cr0 + s0; l1 = l1 * cr1 + s1;
        m0 = mn0; m1 = mn1;
        #pragma unroll
        for (int ni = 0; ni < 8; ni++) {
            accO[ni][0] *= cr0; accO[ni][1] *= cr0;
            accO[ni][2] *= cr1; accO[ni][3] *= cr1;
        }

        // O += P V (split: Ph*Vh + Ph*Vl + Pl*Vh)
        const int vrow7 = (lane & 7) + ((lane & 8) ? 8 : 0);
        const int vcsel = ((lane & 16) ? 1 : 0);
        #pragma unroll
        for (int kt = 0; kt < 4; kt++) {
            uint32_t pa[4] = {pha[2 * kt], phb[2 * kt], pha[2 * kt + 1], phb[2 * kt + 1]};
            uint32_t la[4] = {pla[2 * kt], plb[2 * kt], pla[2 * kt + 1], plb[2 * kt + 1]};
            #pragma unroll
            for (int p = 0; p < 4; p++) {
                uint32_t vh[4], vl[4];
                uint32_t svh = (uint32_t)__cvta_generic_to_shared(
                    Vhs + (kt * 16 + vrow7) * 144 + (p * 2 + vcsel) * 16);
                uint32_t svl = (uint32_t)__cvta_generic_to_shared(
                    Vls + (kt * 16 + vrow7) * 144 + (p * 2 + vcsel) * 16);
                asm volatile("ldmatrix.sync.aligned.m8n8.x4.trans.shared.b16 {%0,%1,%2,%3},[%4];"
                             : "=r"(vh[0]), "=r"(vh[1]), "=r"(vh[2]), "=r"(vh[3]) : "r"(svh));
                asm volatile("ldmatrix.sync.aligned.m8n8.x4.trans.shared.b16 {%0,%1,%2,%3},[%4];"
                             : "=r"(vl[0]), "=r"(vl[1]), "=r"(vl[2]), "=r"(vl[3]) : "r"(svl));
                mma16816(accO[2 * p],     pa, vh);
                mma16816(accO[2 * p + 1], pa, vh + 2);
                mma16816(accO[2 * p],     pa, vl);
                mma16816(accO[2 * p + 1], pa, vl + 2);
                mma16816(accO[2 * p],     la, vh);
                mma16816(accO[2 * p + 1], la, vh + 2);
            }
        }
        __syncthreads();
    }

    // epilogue: O / l, split-bf16 scatter into o_ext rows
    float inv0 = 1.0f / l0, inv1 = 1.0f / l1;
    const int ilo = wid * 16 + (lane >> 2);
    const int ihi = ilo + 8;
    const size_t rlo = (size_t)(b * N_ + tok[ilo]) * 1536 + h * 64 + (lane & 3) * 2;
    const size_t rhi = (size_t)(b * N_ + tok[ihi]) * 1536 + h * 64 + (lane & 3) * 2;
    #pragma unroll
    for (int ni = 0; ni < 8; ni++) {
        float o0 = accO[ni][0] * inv0, o1 = accO[ni][1] * inv0;
        float o2 = accO[ni][2] * inv1, o3 = accO[ni][3] * inv1;
        __nv_bfloat16 h0, q0, h1, q1, h2, q2, h3, q3;
        bsplit(o0, h0, q0); bsplit(o1, h1, q1);
        bsplit(o2, h2, q2); bsplit(o3, h3, q3);
        __nv_bfloat162 hiA; hiA.x = h0; hiA.y = h1;
        __nv_bfloat162 loA; loA.x = q0; loA.y = q1;
        __nv_bfloat162 hiB; hiB.x = h2; hiB.y = h3;
        __nv_bfloat162 loB; loB.x = q2; loB.y = q3;
        *(__nv_bfloat162*)(g_o_ext + rlo + ni * 8)        = hiA;
        *(__nv_bfloat162*)(g_o_ext + rlo + ni * 8 + 512)  = hiA;
        *(__nv_bfloat162*)(g_o_ext + rlo + ni * 8 + 1024) = loA;
        *(__nv_bfloat162*)(g_o_ext + rhi + ni * 8)        = hiB;
        *(__nv_bfloat162*)(g_o_ext + rhi + ni * 8 + 512)  = hiB;
        *(__nv_bfloat162*)(g_o_ext + rhi + ni * 8 + 1024) = loB;
    }
}

// ---------------- auxiliary outputs (assigned, rp) if harness concatenates ----------------
__global__ void extras_kernel(float* __restrict__ outp, int write_rp) {
    int i = blockIdx.x * 256 + threadIdx.x;
    if (i < MT) {
        outp[MT * D_ + i] = (float)g_assigned[i];
        if (write_rp) outp[MT * D_ + MT + i] = g_rp[i];
    }
}

// ---------------- launch ----------------
extern "C" void kernel_launch(void* const* d_in, const int* in_sizes, int n_in,
                              void* d_out, int out_size) {
    const float* x     = (const float*)d_in[0];
    const float* r_w   = (const float*)d_in[1];
    const float* r_b   = (const float*)d_in[2];
    const float* g1    = (const float*)d_in[3];
    const float* b1    = (const float*)d_in[4];
    const float* g2    = (const float*)d_in[5];
    const float* b2    = (const float*)d_in[6];
    const float* w_qkv = (const float*)d_in[7];
    const float* w_o   = (const float*)d_in[8];
    const float* b_o   = (const float*)d_in[9];
    const float* w1    = (const float*)d_in[10];
    const float* b1f   = (const float*)d_in[11];
    const float* w2    = (const float*)d_in[12];
    const float* b2f   = (const float*)d_in[13];
    const float* alpha = (const float*)d_in[14];
    float* out = (float*)d_out;

    static const int FATTN_SMEM = 2 * 64 * 400 + 2 * 64 * 144;   // 69632
    cudaFuncSetAttribute(fattn_kernel, cudaFuncAttributeMaxDynamicSharedMemorySize, FATTN_SMEM);

    router_kernel<<<MT / 8, 256>>>(x, r_w, r_b);
    assign_kernel<<<B_, 1024>>>();
    zfill_kernel<<<MT, 256>>>();

    wconv_kernel<0><<<(512 * 1536 + 255) / 256, 256>>>(w_qkv, 512 * 1536);
    wconv_kernel<1><<<(512 * 512 + 255) / 256, 256>>>(w_o, 512 * 512);
    wconv_kernel<2><<<(512 * 2048 + 255) / 256, 256>>>(w1, 512 * 2048);
    wconv_kernel<3><<<(2048 * 512 + 255) / 256, 256>>>(w2, 2048 * 512);

    ln_kernel<0><<<MT, 256>>>(x, g1, b1);
    tgemm_kernel<0, 1536, 1536><<<dim3(12, 64), 256>>>(nullptr, nullptr, nullptr, nullptr);
    fattn_kernel<<<dim3(80, B_), 128, FATTN_SMEM>>>();
    tgemm_kernel<1, 1536, 512><<<dim3(4, 64), 256>>>(b_o, x, nullptr, nullptr);
    ln_kernel<1><<<MT, 256>>>(x, g2, b2);
    tgemm_kernel<2, 1536, 2048><<<dim3(16, 64), 256>>>(b1f, nullptr, nullptr, nullptr);
    tgemm_kernel<3, 6144, 512><<<dim3(4, 64), 256>>>(b2f, nullptr, alpha, out);

    if (out_size >= MT * D_ + MT) {
        int write_rp = (out_size >= MT * D_ + 2 * MT) ? 1 : 0;
        extras_kernel<<<(MT + 255) / 256, 256>>>(out, write_rp);
    }
}

// round 8
// speedup vs baseline: 4.4841x; 1.4005x over previous
#include <cuda_runtime.h>
#include <cuda_bf16.h>
#include <cstdint>
#include <math.h>

#define B_  4
#define N_  2048
#define D_  512
#define H_  8
#define E_  4
#define MT  (B_*N_)

__device__ float g_probs[MT*E_];
__device__ int   g_dtok[MT];
__device__ int   g_assigned[MT];
__device__ int   g_perm[MT];
__device__ float g_rp[MT];
__device__ float g_z [MT*D_];
__device__ float g_fpart[4][B_*512*512];
__device__ __nv_bfloat16 g_h_ext  [MT*1536];
__device__ __nv_bfloat16 g_o_ext  [MT*1536];
__device__ __nv_bfloat16 g_hm_ext [MT*1536];
__device__ __nv_bfloat16 g_hid_ext[(size_t)MT*6144];   // permuted rows
__device__ __nv_bfloat16 g_qext[(size_t)B_*H_*N_*192];
__device__ __nv_bfloat16 g_kext[(size_t)B_*H_*N_*192];
__device__ __nv_bfloat16 g_vh [(size_t)B_*H_*N_*64];
__device__ __nv_bfloat16 g_vl [(size_t)B_*H_*N_*64];
__device__ __nv_bfloat16 g_wqkv_ext[1536*1536];
__device__ __nv_bfloat16 g_wo_ext  [1536*512];
__device__ __nv_bfloat16 g_w1_ext  [1536*2048];
__device__ __nv_bfloat16 g_w2_ext  [6144*512];

__constant__ int c_head[80] = {
    0,0,0,0,0,0,0,0,0,0,0,0,0,0,0,0,0,0,0,0,0,0,0,0,0,0,0,0,0,0,0,0,
    1,1,1,1,1,1,1,1,1,1,1,1,1,1,1,1,
    2,2,2,2,2,2,2,2, 3,3,3,3,3,3,3,3,
    4,4,4,4, 5,5,5,5, 6,6,6,6, 7,7,7,7};
__constant__ int c_chunk[80] = {
    0,1,2,3,4,5,6,7,8,9,10,11,12,13,14,15,16,17,18,19,20,21,22,23,24,25,26,27,28,29,30,31,
    0,1,2,3,4,5,6,7,8,9,10,11,12,13,14,15,
    0,1,2,3,4,5,6,7, 0,1,2,3,4,5,6,7,
    0,1,2,3, 0,1,2,3, 0,1,2,3, 0,1,2,3};

__device__ __forceinline__ void bsplit(float v, __nv_bfloat16& h, __nv_bfloat16& l) {
    h = __float2bfloat16(v);
    l = __float2bfloat16(v - __bfloat162float(h));
}
__device__ __forceinline__ uint32_t packb(__nv_bfloat16 a, __nv_bfloat16 b) {
    __nv_bfloat162 t; t.x = a; t.y = b; return *(uint32_t*)&t;
}

__global__ void router_kernel(const float* __restrict__ x,
                              const float* __restrict__ rw,
                              const float* __restrict__ rb) {
    int warp = threadIdx.x >> 5, lane = threadIdx.x & 31;
    int t = blockIdx.x * 8 + warp;
    const float* xr = x + t * D_;
    double a0 = 0, a1 = 0, a2 = 0, a3 = 0;
    for (int j = lane; j < D_; j += 32) {
        double xv = (double)xr[j];
        const float* w = rw + j * E_;
        a0 += xv * (double)w[0]; a1 += xv * (double)w[1];
        a2 += xv * (double)w[2]; a3 += xv * (double)w[3];
    }
    #pragma unroll
    for (int o = 16; o > 0; o >>= 1) {
        a0 += __shfl_down_sync(0xffffffffu, a0, o);
        a1 += __shfl_down_sync(0xffffffffu, a1, o);
        a2 += __shfl_down_sync(0xffffffffu, a2, o);
        a3 += __shfl_down_sync(0xffffffffu, a3, o);
    }
    if (lane == 0) {
        double l0 = a0 + (double)rb[0], l1 = a1 + (double)rb[1];
        double l2 = a2 + (double)rb[2], l3 = a3 + (double)rb[3];
        double mx = fmax(fmax(l0, l1), fmax(l2, l3));
        double e0 = exp(l0 - mx), e1 = exp(l1 - mx), e2 = exp(l2 - mx), e3 = exp(l3 - mx);
        double s = e0 + e1 + e2 + e3;
        float* p = g_probs + t * 4;
        p[0] = (float)(e0 / s); p[1] = (float)(e1 / s);
        p[2] = (float)(e2 / s); p[3] = (float)(e3 / s);
    }
}

__device__ __forceinline__ unsigned int f2ord(float f) {
    unsigned int u = __float_as_uint(f);
    return (u & 0x80000000u) ? ~u : (u | 0x80000000u);
}

__global__ __launch_bounds__(1024) void assign_kernel() {
    const int b = blockIdx.x, tid = threadIdx.x;
    __shared__ unsigned long long key[N_];
    __shared__ int sas[N_];
    __shared__ int cnt[4];
    sas[tid] = -1; sas[tid + 1024] = -1;
    if (tid < 4) cnt[tid] = 0;
    __syncthreads();
    const int capByE[4] = {1024, 512, 256, 256};
    for (int p = 0; p < 4; p++) {
        const int e = 3 - p, cap = capByE[e];
        #pragma unroll
        for (int ii = 0; ii < 2; ii++) {
            int i = tid + ii * 1024;
            float pr = (sas[i] < 0) ? g_probs[(b * N_ + i) * E_ + e] : -1.0f;
            key[i] = ((unsigned long long)f2ord(pr) << 32) | (unsigned int)(0xFFFFFFFFu - (unsigned)i);
        }
        __syncthreads();
        for (int k = 2; k <= N_; k <<= 1) {
            for (int j = k >> 1; j > 0; j >>= 1) {
                #pragma unroll
                for (int ii = 0; ii < 2; ii++) {
                    int i = tid + ii * 1024, ixj = i ^ j;
                    if (ixj > i) {
                        unsigned long long a = key[i], c = key[ixj];
                        bool sw = ((i & k) == 0) ? (a < c) : (a > c);
                        if (sw) { key[i] = c; key[ixj] = a; }
                    }
                }
                __syncthreads();
            }
        }
        #pragma unroll
        for (int ii = 0; ii < 2; ii++) {
            int pos = tid + ii * 1024;
            if (pos < cap) {
                unsigned long long kk = key[pos];
                if ((unsigned int)(kk >> 32) >= 0x80000000u)
                    sas[(int)(0xFFFFFFFFu - (unsigned int)(kk & 0xFFFFFFFFu))] = e;
            }
        }
        __syncthreads();
    }
    const int startE[4] = {1024, 512, 256, 0};
    #pragma unroll
    for (int ii = 0; ii < 2; ii++) {
        int i = tid + ii * 1024;
        int a = sas[i]; if (a < 0) a = 0;
        int gi = b * N_ + i;
        g_assigned[gi] = a;
        g_dtok[gi] = 64 << a;
        g_rp[gi] = g_probs[gi * E_ + a];
        int pos = startE[a] + atomicAdd(&cnt[a], 1);
        g_perm[b * N_ + pos] = i;
    }
}

// R5 zfill: zero masked cols of o_ext (dense O-proj reads full K)
__global__ void zfill_kernel() {
    int m = blockIdx.x;
    int c = threadIdx.x * 2;
    int dt = g_dtok[m];
    if (c >= dt) {
        __nv_bfloat162 z; z.x = __float2bfloat16(0.0f); z.y = z.x;
        size_t base = (size_t)m * 1536 + c;
        *(__nv_bfloat162*)(g_o_ext + base)        = z;
        *(__nv_bfloat162*)(g_o_ext + base + 512)  = z;
        *(__nv_bfloat162*)(g_o_ext + base + 1024) = z;
    }
}

// after z is final: masked cols of out = z (grouped FFN2 writes only unmasked)
__global__ void prepout_kernel(float* __restrict__ outp) {
    int m = blockIdx.x;
    int n = threadIdx.x * 2;
    if (n >= g_dtok[m]) {
        *(float2*)(outp + (size_t)m * 512 + n) = *(const float2*)(g_z + (size_t)m * 512 + n);
    }
}

template<int PASS>
__global__ __launch_bounds__(256) void ln_kernel(const float* __restrict__ xin,
                                                 const float* __restrict__ gam,
                                                 const float* __restrict__ bet) {
    const int t = blockIdx.x;
    const float* r = (PASS == 0 ? xin : g_z) + t * D_;
    const int tid = threadIdx.x, lane = tid & 31, wid = tid >> 5;
    __shared__ float red[8];
    __shared__ float s_mu, s_rstd;
    float x0 = r[tid], x1 = r[tid + 256];
    float s = x0 + x1;
    #pragma unroll
    for (int o = 16; o > 0; o >>= 1) s += __shfl_down_sync(0xffffffffu, s, o);
    if (lane == 0) red[wid] = s;
    __syncthreads();
    if (tid == 0) {
        float tt = 0;
        #pragma unroll
        for (int w = 0; w < 8; w++) tt += red[w];
        s_mu = tt * (1.0f / 512.0f);
    }
    __syncthreads();
    float mu = s_mu;
    float d0 = x0 - mu, d1 = x1 - mu;
    float q = d0 * d0 + d1 * d1;
    #pragma unroll
    for (int o = 16; o > 0; o >>= 1) q += __shfl_down_sync(0xffffffffu, q, o);
    if (lane == 0) red[wid] = q;
    __syncthreads();
    if (tid == 0) {
        float tt = 0;
        #pragma unroll
        for (int w = 0; w < 8; w++) tt += red[w];
        s_rstd = rsqrtf(tt * (1.0f / 512.0f) + 1e-5f);
    }
    __syncthreads();
    float rstd = s_rstd;
    int dt = g_dtok[t];
    float y0 = (tid < dt)       ? (d0 * rstd * gam[tid]       + bet[tid])       : 0.0f;
    float y1 = (tid + 256 < dt) ? (d1 * rstd * gam[tid + 256] + bet[tid + 256]) : 0.0f;
    __nv_bfloat16 h0, l0, h1, l1;
    bsplit(y0, h0, l0); bsplit(y1, h1, l1);
    __nv_bfloat16* e = (PASS == 0 ? g_h_ext : g_hm_ext) + (size_t)t * 1536;
    e[tid]        = h0; e[tid + 512]        = h0; e[tid + 1024]        = l0;
    e[tid + 256]  = h1; e[tid + 256 + 512]  = h1; e[tid + 256 + 1024]  = l1;
}

template<int W>
__global__ void wconv_kernel(const float* __restrict__ Wsrc, int total) {
    __nv_bfloat16* ext = (W == 0) ? g_wqkv_ext : (W == 1) ? g_wo_ext : (W == 2) ? g_w1_ext : g_w2_ext;
    int i = blockIdx.x * 256 + threadIdx.x;
    if (i >= total) return;
    __nv_bfloat16 h, l;
    bsplit(Wsrc[i], h, l);
    ext[i] = h; ext[total + i] = l; ext[2 * total + i] = h;
}

__device__ __forceinline__ void mma16816(float* c, const uint32_t* a, const uint32_t* b) {
    asm volatile("mma.sync.aligned.m16n8k16.row.col.f32.bf16.bf16.f32 "
                 "{%0,%1,%2,%3},{%4,%5,%6,%7},{%8,%9},{%0,%1,%2,%3};"
                 : "+f"(c[0]), "+f"(c[1]), "+f"(c[2]), "+f"(c[3])
                 : "r"(a[0]), "r"(a[1]), "r"(a[2]), "r"(a[3]), "r"(b[0]), "r"(b[1]));
}

// ---------------- R5 dense tensor GEMM (QKV + O-proj) ----------------
template<int K3, int NC>
__device__ __forceinline__ void stage_load(const __nv_bfloat16* __restrict__ Ag,
                                           const __nv_bfloat16* __restrict__ Bg,
                                           unsigned char* As, unsigned char* Bs,
                                           int slab, int tid) {
    #pragma unroll
    for (int i = 0; i < 2; i++) {
        int id = tid + i * 256;
        int r = id >> 2, c = id & 3;
        const __nv_bfloat16* g = Ag + (size_t)r * K3 + slab * 32 + c * 8;
        uint32_t s = (uint32_t)__cvta_generic_to_shared(As + r * 64 + ((c ^ ((r >> 1) & 3)) << 4));
        asm volatile("cp.async.cg.shared.global [%0],[%1],16;\n" :: "r"(s), "l"(g));
    }
    #pragma unroll
    for (int i = 0; i < 2; i++) {
        int id = tid + i * 256;
        int r = id >> 4, c = id & 15;
        const __nv_bfloat16* g = Bg + (size_t)(slab * 32 + r) * NC + c * 8;
        uint32_t s = (uint32_t)__cvta_generic_to_shared(Bs + r * 256 + ((c ^ (r & 7)) << 4));
        asm volatile("cp.async.cg.shared.global [%0],[%1],16;\n" :: "r"(s), "l"(g));
    }
    asm volatile("cp.async.commit_group;\n");
}

template<int EPI, int K3, int NC>
__global__ void __launch_bounds__(256, 2) tgemm_kernel(const float* __restrict__ bias,
                                                       const float* __restrict__ resid) {
    const __nv_bfloat16* Aext = (EPI == 0) ? g_h_ext : g_o_ext;
    const __nv_bfloat16* Bext = (EPI == 0) ? g_wqkv_ext : g_wo_ext;
    __shared__ __align__(16) unsigned char smA[2][128 * 64];
    __shared__ __align__(16) unsigned char smB[2][32 * 256];
    const int tid = threadIdx.x, lane = tid & 31, wid = tid >> 5;
    const int bm = blockIdx.y * 128, bn = blockIdx.x * 128;
    const int wm = (wid >> 2) * 64;
    const int widn = wid & 3;
    const __nv_bfloat16* Ag = Aext + (size_t)bm * K3;
    const __nv_bfloat16* Bg = Bext + bn;

    float acc[4][4][4];
    #pragma unroll
    for (int i = 0; i < 4; i++)
        #pragma unroll
        for (int j = 0; j < 4; j++)
            #pragma unroll
            for (int k = 0; k < 4; k++) acc[i][j][k] = 0.0f;

    constexpr int NS = K3 / 32;
    stage_load<K3, NC>(Ag, Bg, smA[0], smB[0], 0, tid);

    #pragma unroll 1
    for (int s = 0; s < NS; s++) {
        int cur = s & 1;
        if (s + 1 < NS) {
            stage_load<K3, NC>(Ag, Bg, smA[cur ^ 1], smB[cur ^ 1], s + 1, tid);
            asm volatile("cp.async.wait_group 1;\n");
        } else {
            asm volatile("cp.async.wait_group 0;\n");
        }
        __syncthreads();
        unsigned char* As = smA[cur];
        unsigned char* Bs = smB[cur];
        #pragma unroll
        for (int kk = 0; kk < 2; kk++) {
            uint32_t af[4][4], bfr[4][2];
            #pragma unroll
            for (int mi = 0; mi < 4; mi++) {
                int r = wm + mi * 16 + (lane & 7) + ((lane & 8) ? 8 : 0);
                int c = kk * 2 + ((lane & 16) ? 1 : 0);
                uint32_t sa = (uint32_t)__cvta_generic_to_shared(
                    As + r * 64 + ((c ^ ((r >> 1) & 3)) << 4));
                asm volatile("ldmatrix.sync.aligned.m8n8.x4.shared.b16 {%0,%1,%2,%3},[%4];"
                             : "=r"(af[mi][0]), "=r"(af[mi][1]), "=r"(af[mi][2]), "=r"(af[mi][3])
                             : "r"(sa));
            }
            #pragma unroll
            for (int np = 0; np < 2; np++) {
                int kr = kk * 16 + (lane & 7) + ((lane & 8) ? 8 : 0);
                int c = widn * 4 + np * 2 + ((lane & 16) ? 1 : 0);
                uint32_t sb = (uint32_t)__cvta_generic_to_shared(
                    Bs + kr * 256 + ((c ^ (kr & 7)) << 4));
                asm volatile("ldmatrix.sync.aligned.m8n8.x4.trans.shared.b16 {%0,%1,%2,%3},[%4];"
                             : "=r"(bfr[np * 2][0]), "=r"(bfr[np * 2][1]),
                               "=r"(bfr[np * 2 + 1][0]), "=r"(bfr[np * 2 + 1][1])
                             : "r"(sb));
            }
            #pragma unroll
            for (int mi = 0; mi < 4; mi++)
                #pragma unroll
                for (int ni = 0; ni < 4; ni++)
                    mma16816(acc[mi][ni], af[mi], bfr[ni]);
        }
        __syncthreads();
    }

    const int l4 = lane >> 2, l2 = (lane & 3) * 2;
    #pragma unroll
    for (int mi = 0; mi < 4; mi++) {
        #pragma unroll
        for (int hh = 0; hh < 2; hh++) {
            int m = bm + wm + mi * 16 + l4 + hh * 8;
            int dt = g_dtok[m];
            #pragma unroll
            for (int ni = 0; ni < 4; ni++) {
                int n = bn + widn * 32 + ni * 8 + l2;
                float v0 = acc[mi][ni][hh * 2 + 0];
                float v1 = acc[mi][ni][hh * 2 + 1];
                if (EPI == 0) {
                    int chunk = n >> 9, f = n & 511;
                    int head = f >> 6, d = f & 63, bb = m >> 11, tokv = m & 2047;
                    bool on = (f < dt);
                    float w0 = on ? v0 : 0.0f;
                    float w1 = on ? v1 : 0.0f;
                    __nv_bfloat16 hh0, ll0, hh1, ll1;
                    bsplit(w0, hh0, ll0); bsplit(w1, hh1, ll1);
                    __nv_bfloat162 hi2; hi2.x = hh0; hi2.y = hh1;
                    __nv_bfloat162 lo2; lo2.x = ll0; lo2.y = ll1;
                    size_t base = (size_t)((bb * H_ + head) * N_ + tokv);
                    if (chunk == 0) {
                        __nv_bfloat16* p = g_qext + base * 192 + d;
                        *(__nv_bfloat162*)(p)       = hi2;
                        *(__nv_bfloat162*)(p + 64)  = hi2;
                        *(__nv_bfloat162*)(p + 128) = lo2;
                    } else if (chunk == 1) {
                        __nv_bfloat16* p = g_kext + base * 192 + d;
                        *(__nv_bfloat162*)(p)       = hi2;
                        *(__nv_bfloat162*)(p + 64)  = lo2;
                        *(__nv_bfloat162*)(p + 128) = hi2;
                    } else {
                        *(__nv_bfloat162*)(g_vh + base * 64 + d) = hi2;
                        *(__nv_bfloat162*)(g_vl + base * 64 + d) = lo2;
                    }
                } else {
                    float w0 = v0 + bias[n];
                    float w1 = v1 + bias[n + 1];
                    if (n >= dt) w0 = 0.0f;
                    if (n + 1 >= dt) w1 = 0.0f;
                    const float2 xr = *(const float2*)(resid + (size_t)m * 512 + n);
                    float2 o; o.x = xr.x + w0; o.y = xr.y + w1;
                    *(float2*)(g_z + (size_t)m * 512 + n) = o;
                }
            }
        }
    }
}

// ---------------- grouped FFN GEMMs (EPI 2: FFN1, EPI 3: FFN2 + split-K) ----------------
template<int EPI>
__global__ void __launch_bounds__(256, 2) ggemm_kernel(const float* __restrict__ bias,
                                                       const float* __restrict__ alpha,
                                                       float* __restrict__ outp) {
    const __nv_bfloat16* Aext = (EPI == 2) ? g_hm_ext : g_hid_ext;
    const __nv_bfloat16* Bext = (EPI == 2) ? g_w1_ext : g_w2_ext;
    constexpr int NC  = (EPI == 2) ? 2048 : 512;
    constexpr int SEG = (EPI == 3) ? 2048 : 512;
    constexpr size_t AROW = 3 * SEG;
    constexpr int TN0v = (EPI == 2) ? 2 : 1;
    constexpr int TN1v = (EPI == 2) ? 4 : 1;
    constexpr int TN2v = (EPI == 2) ? 8 : 2;
    constexpr int TN3v = (EPI == 2) ? 16 : 4;
    constexpr int TS3v = (EPI == 3) ? 4 : 1;
    constexpr int TS2v = (EPI == 3) ? 2 : 1;
    constexpr int C3 = 2 * TN3v * TS3v, C2 = 2 * TN2v * TS2v, C1 = 4 * TN1v;

    const int tid = threadIdx.x, lane = tid & 31, wid = tid >> 5;
    const int b = blockIdx.y;
    int idx = blockIdx.x;
    int e, loc, TN, TS;
    if (idx < C3)                 { e = 3; loc = idx;                  TN = TN3v; TS = TS3v; }
    else if (idx < C3 + C2)       { e = 2; loc = idx - C3;             TN = TN2v; TS = TS2v; }
    else if (idx < C3 + C2 + C1)  { e = 1; loc = idx - (C3 + C2);      TN = TN1v; TS = 1; }
    else                          { e = 0; loc = idx - (C3 + C2 + C1); TN = TN0v; TS = 1; }
    const int mt = loc / (TN * TS);
    int rem = loc - mt * (TN * TS);
    const int nt = rem / TS;
    const int sp = rem - nt * TS;
    const int d = 64 << e;
    const int ld = ((EPI == 3) ? 8 : 6) + e;
    const int dm = (1 << ld) - 1;
    const int NStot = (3 << ld) >> 5;
    const int per = NStot / TS;
    const int slab0 = sp * per, slab1 = slab0 + per;
    const int segstart = (e == 0) ? 1024 : (e == 1) ? 512 : (e == 2) ? 256 : 0;

    __shared__ __align__(16) unsigned char smA[2][128 * 64];
    __shared__ __align__(16) unsigned char smB[2][32 * 256];
    __shared__ int sA[128], sT[128];
    if (tid < 128) {
        int pos = segstart + mt * 128 + tid;
        int pv = g_perm[b * 2048 + pos];
        sT[tid] = pv;
        sA[tid] = (EPI == 3) ? (b * 2048 + pos) : (b * 2048 + pv);
    }
    __syncthreads();

    const int rA0 = tid >> 2, cA = tid & 3, rA1 = rA0 + 64;
    const __nv_bfloat16* Ap0 = Aext + (size_t)sA[rA0] * AROW + cA * 8;
    const __nv_bfloat16* Ap1 = Aext + (size_t)sA[rA1] * AROW + cA * 8;
    const int oA0 = rA0 * 64 + ((cA ^ ((rA0 >> 1) & 3)) << 4);
    const int oA1 = rA1 * 64 + ((cA ^ ((rA1 >> 1) & 3)) << 4);
    const int rB0 = tid >> 4, cB = tid & 15, rB1 = rB0 + 16;
    const int bc = nt * 128 + cB * 8;
    const __nv_bfloat16* Bp0 = Bext + (size_t)rB0 * NC + bc;
    const __nv_bfloat16* Bp1 = Bext + (size_t)rB1 * NC + bc;
    const int oB0 = rB0 * 256 + ((cB ^ (rB0 & 7)) << 4);
    const int oB1 = rB1 * 256 + ((cB ^ (rB1 & 7)) << 4);

    const int wm = (wid >> 2) * 64;
    const int widn = wid & 3;

    float acc[4][4][4];
    #pragma unroll
    for (int i = 0; i < 4; i++)
        #pragma unroll
        for (int jx = 0; jx < 4; jx++)
            #pragma unroll
            for (int k = 0; k < 4; k++) acc[i][jx][k] = 0.0f;

    #define GSTAGE(buf, slab) { \
        int kk_ = (slab) * 32; int kb_ = ((kk_ >> ld) * SEG) + (kk_ & dm); \
        uint32_t ba_ = (uint32_t)__cvta_generic_to_shared(smA[buf]); \
        uint32_t bb_ = (uint32_t)__cvta_generic_to_shared(smB[buf]); \
        asm volatile("cp.async.cg.shared.global [%0],[%1],16;\n" :: "r"(ba_ + oA0), "l"(Ap0 + kb_)); \
        asm volatile("cp.async.cg.shared.global [%0],[%1],16;\n" :: "r"(ba_ + oA1), "l"(Ap1 + kb_)); \
        asm volatile("cp.async.cg.shared.global [%0],[%1],16;\n" :: "r"(bb_ + oB0), "l"(Bp0 + (size_t)kb_ * NC)); \
        asm volatile("cp.async.cg.shared.global [%0],[%1],16;\n" :: "r"(bb_ + oB1), "l"(Bp1 + (size_t)kb_ * NC)); \
        asm volatile("cp.async.commit_group;\n"); }

    GSTAGE(0, slab0);

    #pragma unroll 1
    for (int s = slab0; s < slab1; s++) {
        int cur = (s - slab0) & 1;
        if (s + 1 < slab1) {
            GSTAGE(cur ^ 1, s + 1);
            asm volatile("cp.async.wait_group 1;\n");
        } else {
            asm volatile("cp.async.wait_group 0;\n");
        }
        __syncthreads();
        unsigned char* As = smA[cur];
        unsigned char* Bs = smB[cur];
        #pragma unroll
        for (int kk = 0; kk < 2; kk++) {
            uint32_t af[4][4], bfr[4][2];
            #pragma unroll
            for (int mi = 0; mi < 4; mi++) {
                int r = wm + mi * 16 + (lane & 7) + ((lane & 8) ? 8 : 0);
                int c = kk * 2 + ((lane & 16) ? 1 : 0);
                uint32_t sa = (uint32_t)__cvta_generic_to_shared(
                    As + r * 64 + ((c ^ ((r >> 1) & 3)) << 4));
                asm volatile("ldmatrix.sync.aligned.m8n8.x4.shared.b16 {%0,%1,%2,%3},[%4];"
                             : "=r"(af[mi][0]), "=r"(af[mi][1]), "=r"(af[mi][2]), "=r"(af[mi][3])
                             : "r"(sa));
            }
            #pragma unroll
            for (int np = 0; np < 2; np++) {
                int kr = kk * 16 + (lane & 7) + ((lane & 8) ? 8 : 0);
                int c = widn * 4 + np * 2 + ((lane & 16) ? 1 : 0);
                uint32_t sb = (uint32_t)__cvta_generic_to_shared(
                    Bs + kr * 256 + ((c ^ (kr & 7)) << 4));
                asm volatile("ldmatrix.sync.aligned.m8n8.x4.trans.shared.b16 {%0,%1,%2,%3},[%4];"
                             : "=r"(bfr[np * 2][0]), "=r"(bfr[np * 2][1]),
                               "=r"(bfr[np * 2 + 1][0]), "=r"(bfr[np * 2 + 1][1])
                             : "r"(sb));
            }
            #pragma unroll
            for (int mi = 0; mi < 4; mi++)
                #pragma unroll
                for (int ni = 0; ni < 4; ni++)
                    mma16816(acc[mi][ni], af[mi], bfr[ni]);
        }
        __syncthreads();
    }

    const int l4 = lane >> 2, l2 = (lane & 3) * 2;

    if (EPI == 3 && TS > 1) {
        #pragma unroll
        for (int mi = 0; mi < 4; mi++) {
            #pragma unroll
            for (int hh = 0; hh < 2; hh++) {
                int mrl = wm + mi * 16 + l4 + hh * 8;
                int pos = segstart + mt * 128 + mrl;
                #pragma unroll
                for (int ni = 0; ni < 4; ni++) {
                    int n = nt * 128 + widn * 32 + ni * 8 + l2;
                    float2 v; v.x = acc[mi][ni][hh * 2]; v.y = acc[mi][ni][hh * 2 + 1];
                    *(float2*)&g_fpart[sp][((b << 9) + pos) * 512 + n] = v;
                }
            }
        }
        return;
    }

    float aval = 0.0f;
    if (EPI == 3) aval = alpha[0];

    #pragma unroll
    for (int mi = 0; mi < 4; mi++) {
        #pragma unroll
        for (int hh = 0; hh < 2; hh++) {
            int mrl = wm + mi * 16 + l4 + hh * 8;
            int tok = sT[mrl];
            #pragma unroll
            for (int ni = 0; ni < 4; ni++) {
                int n = nt * 128 + widn * 32 + ni * 8 + l2;
                float v0 = acc[mi][ni][hh * 2 + 0];
                float v1 = acc[mi][ni][hh * 2 + 1];
                if (EPI == 2) {
                    if (n < 4 * d) {
                        int pos = segstart + mt * 128 + mrl;
                        size_t row = (size_t)(b * 2048 + pos) * 6144;
                        float w = v0 + bias[n];
                        float c1 = 0.7978845608028654f * (w + 0.044715f * w * w * w);
                        float h0 = 0.5f * w * (1.0f + tanhf(c1));
                        w = v1 + bias[n + 1];
                        c1 = 0.7978845608028654f * (w + 0.044715f * w * w * w);
                        float h1 = 0.5f * w * (1.0f + tanhf(c1));
                        __nv_bfloat16 a0, b0, a1, b1;
                        bsplit(h0, a0, b0); bsplit(h1, a1, b1);
                        __nv_bfloat162 hi; hi.x = a0; hi.y = a1;
                        __nv_bfloat162 lo; lo.x = b0; lo.y = b1;
                        *(__nv_bfloat162*)(g_hid_ext + row + n)        = hi;
                        *(__nv_bfloat162*)(g_hid_ext + row + n + 2048) = hi;
                        *(__nv_bfloat162*)(g_hid_ext + row + n + 4096) = lo;
                    }
                } else {
                    if (n < d) {
                        size_t row = (size_t)(b * 2048 + tok) * 512;
                        float gm = aval * g_rp[b * 2048 + tok] + 1.0f;
                        float w0 = v0 + bias[n];
                        float w1 = v1 + bias[n + 1];
                        const float2 zz = *(const float2*)(g_z + row + n);
                        float2 o; o.x = zz.x + gm * w0; o.y = zz.y + gm * w1;
                        *(float2*)(outp + row + n) = o;
                    }
                }
            }
        }
    }
    #undef GSTAGE
}

__global__ void reduce3_kernel(const float* __restrict__ b2f,
                               const float* __restrict__ alpha,
                               float* __restrict__ outp) {
    int rowid = blockIdx.x;
    int b = rowid >> 9, pos = rowid & 511;
    int ns = (pos < 256) ? 4 : 2;
    int d = (pos < 256) ? 512 : 256;
    int tok = g_perm[b * 2048 + pos];
    float gm = alpha[0] * g_rp[b * 2048 + tok] + 1.0f;
    size_t row = (size_t)(b * 2048 + tok) * 512;
    int base = ((b << 9) + pos) * 512;
    for (int n = threadIdx.x; n < d; n += 256) {
        float s = g_fpart[0][base + n] + g_fpart[1][base + n];
        if (ns == 4) s += g_fpart[2][base + n] + g_fpart[3][base + n];
        s += b2f[n];
        outp[row + n] = g_z[row + n] + gm * s;
    }
}

// ---------------- R5 tensor-core flash attention ----------------
__global__ void __launch_bounds__(128, 3) fattn_kernel() {
    const int b = blockIdx.y;
    const int slot = blockIdx.x;
    const int h = c_head[slot];
    const int ch = c_chunk[slot];
    extern __shared__ __align__(16) unsigned char sm[];
    unsigned char* Qs  = sm;
    unsigned char* Ks  = sm + 64 * 400;
    unsigned char* Vhs = sm + 2 * 64 * 400;
    unsigned char* Vls = Vhs + 64 * 144;
    __shared__ int tok[64];
    const int tid = threadIdx.x, lane = tid & 31, wid = tid >> 5;

    if (tid < 64) tok[tid] = g_perm[b * N_ + ch * 64 + tid];
    __syncthreads();
    const size_t bh = (size_t)(b * H_ + h) * N_;

    for (int i = tid; i < 64 * 24; i += 128) {
        int r = i / 24, c = i % 24;
        const __nv_bfloat16* g = g_qext + (bh + tok[r]) * 192 + c * 8;
        uint32_t s = (uint32_t)__cvta_generic_to_shared(Qs + r * 400 + c * 16);
        asm volatile("cp.async.cg.shared.global [%0],[%1],16;\n" :: "r"(s), "l"(g));
    }
    asm volatile("cp.async.commit_group;\ncp.async.wait_group 0;\n");
    __syncthreads();

    float accO[8][4];
    #pragma unroll
    for (int i = 0; i < 8; i++)
        #pragma unroll
        for (int j = 0; j < 4; j++) accO[i][j] = 0.0f;
    float m0 = -3.0e38f, m1 = -3.0e38f, l0 = 0.0f, l1 = 0.0f;

    for (int k0 = 0; k0 < N_; k0 += 64) {
        for (int i = tid; i < 64 * 24; i += 128) {
            int r = i / 24, c = i % 24;
            const __nv_bfloat16* g = g_kext + (bh + k0 + r) * 192 + c * 8;
            uint32_t s = (uint32_t)__cvta_generic_to_shared(Ks + r * 400 + c * 16);
            asm volatile("cp.async.cg.shared.global [%0],[%1],16;\n" :: "r"(s), "l"(g));
        }
        for (int i = tid; i < 64 * 8; i += 128) {
            int r = i / 8, c = i % 8;
            const __nv_bfloat16* gh = g_vh + (bh + k0 + r) * 64 + c * 8;
            const __nv_bfloat16* gl = g_vl + (bh + k0 + r) * 64 + c * 8;
            uint32_t sh = (uint32_t)__cvta_generic_to_shared(Vhs + r * 144 + c * 16);
            uint32_t sl = (uint32_t)__cvta_generic_to_shared(Vls + r * 144 + c * 16);
            asm volatile("cp.async.cg.shared.global [%0],[%1],16;\n" :: "r"(sh), "l"(gh));
            asm volatile("cp.async.cg.shared.global [%0],[%1],16;\n" :: "r"(sl), "l"(gl));
        }
        asm volatile("cp.async.commit_group;\ncp.async.wait_group 0;\n");
        __syncthreads();

        float S[8][4];
        #pragma unroll
        for (int i = 0; i < 8; i++)
            #pragma unroll
            for (int j = 0; j < 4; j++) S[i][j] = 0.0f;

        const int qrow = wid * 16 + (lane & 15);
        const int krow7 = (lane & 7) + ((lane & 16) ? 8 : 0);
        const int kcsel = ((lane & 8) ? 1 : 0);
        #pragma unroll
        for (int ks = 0; ks < 12; ks++) {
            uint32_t qf[4];
            uint32_t sa = (uint32_t)__cvta_generic_to_shared(
                Qs + qrow * 400 + (ks * 2 + (lane >> 4)) * 16);
            asm volatile("ldmatrix.sync.aligned.m8n8.x4.shared.b16 {%0,%1,%2,%3},[%4];"
                         : "=r"(qf[0]), "=r"(qf[1]), "=r"(qf[2]), "=r"(qf[3]) : "r"(sa));
            #pragma unroll
            for (int p = 0; p < 4; p++) {
                uint32_t kf[4];
                uint32_t sb = (uint32_t)__cvta_generic_to_shared(
                    Ks + (p * 16 + krow7) * 400 + (ks * 2 + kcsel) * 16);
                asm volatile("ldmatrix.sync.aligned.m8n8.x4.shared.b16 {%0,%1,%2,%3},[%4];"
                             : "=r"(kf[0]), "=r"(kf[1]), "=r"(kf[2]), "=r"(kf[3]) : "r"(sb));
                mma16816(S[2 * p],     qf, kf);
                mma16816(S[2 * p + 1], qf, kf + 2);
            }
        }

        float mx0 = -3.0e38f, mx1 = -3.0e38f;
        #pragma unroll
        for (int ni = 0; ni < 8; ni++) {
            S[ni][0] *= 0.125f; S[ni][1] *= 0.125f; S[ni][2] *= 0.125f; S[ni][3] *= 0.125f;
            mx0 = fmaxf(mx0, fmaxf(S[ni][0], S[ni][1]));
            mx1 = fmaxf(mx1, fmaxf(S[ni][2], S[ni][3]));
        }
        mx0 = fmaxf(mx0, __shfl_xor_sync(0xffffffffu, mx0, 1));
        mx0 = fmaxf(mx0, __shfl_xor_sync(0xffffffffu, mx0, 2));
        mx1 = fmaxf(mx1, __shfl_xor_sync(0xffffffffu, mx1, 1));
        mx1 = fmaxf(mx1, __shfl_xor_sync(0xffffffffu, mx1, 2));
        float mn0 = fmaxf(m0, mx0), mn1 = fmaxf(m1, mx1);
        float cr0 = __expf(m0 - mn0), cr1 = __expf(m1 - mn1);
        float s0 = 0.0f, s1 = 0.0f;
        uint32_t pha[8], phb[8], pla[8], plb[8];
        #pragma unroll
        for (int ni = 0; ni < 8; ni++) {
            float p00 = __expf(S[ni][0] - mn0), p01 = __expf(S[ni][1] - mn0);
            float p10 = __expf(S[ni][2] - mn1), p11 = __expf(S[ni][3] - mn1);
            s0 += p00 + p01; s1 += p10 + p11;
            __nv_bfloat16 h00, l00, h01, l01, h10, l10, h11, l11;
            bsplit(p00, h00, l00); bsplit(p01, h01, l01);
            bsplit(p10, h10, l10); bsplit(p11, h11, l11);
            pha[ni] = packb(h00, h01); phb[ni] = packb(h10, h11);
            pla[ni] = packb(l00, l01); plb[ni] = packb(l10, l11);
        }
        s0 += __shfl_xor_sync(0xffffffffu, s0, 1);
        s0 += __shfl_xor_sync(0xffffffffu, s0, 2);
        s1 += __shfl_xor_sync(0xffffffffu, s1, 1);
        s1 += __shfl_xor_sync(0xffffffffu, s1, 2);
        l0 = l0 * cr0 + s0; l1 = l1 * cr1 + s1;
        m0 = mn0; m1 = mn1;
        #pragma unroll
        for (int ni = 0; ni < 8; ni++) {
            accO[ni][0] *= cr0; accO[ni][1] *= cr0;
            accO[ni][2] *= cr1; accO[ni][3] *= cr1;
        }

        const int vrow7 = (lane & 7) + ((lane & 8) ? 8 : 0);
        const int vcsel = ((lane & 16) ? 1 : 0);
        #pragma unroll
        for (int kt = 0; kt < 4; kt++) {
            uint32_t pa[4] = {pha[2 * kt], phb[2 * kt], pha[2 * kt + 1], phb[2 * kt + 1]};
            uint32_t la[4] = {pla[2 * kt], plb[2 * kt], pla[2 * kt + 1], plb[2 * kt + 1]};
            #pragma unroll
            for (int p = 0; p < 4; p++) {
                uint32_t vh[4], vl[4];
                uint32_t svh = (uint32_t)__cvta_generic_to_shared(
                    Vhs + (kt * 16 + vrow7) * 144 + (p * 2 + vcsel) * 16);
                uint32_t svl = (uint32_t)__cvta_generic_to_shared(
                    Vls + (kt * 16 + vrow7) * 144 + (p * 2 + vcsel) * 16);
                asm volatile("ldmatrix.sync.aligned.m8n8.x4.trans.shared.b16 {%0,%1,%2,%3},[%4];"
                             : "=r"(vh[0]), "=r"(vh[1]), "=r"(vh[2]), "=r"(vh[3]) : "r"(svh));
                asm volatile("ldmatrix.sync.aligned.m8n8.x4.trans.shared.b16 {%0,%1,%2,%3},[%4];"
                             : "=r"(vl[0]), "=r"(vl[1]), "=r"(vl[2]), "=r"(vl[3]) : "r"(svl));
                mma16816(accO[2 * p],     pa, vh);
                mma16816(accO[2 * p + 1], pa, vh + 2);
                mma16816(accO[2 * p],     pa, vl);
                mma16816(accO[2 * p + 1], pa, vl + 2);
                mma16816(accO[2 * p],     la, vh);
                mma16816(accO[2 * p + 1], la, vh + 2);
            }
        }
        __syncthreads();
    }

    float inv0 = 1.0f / l0, inv1 = 1.0f / l1;
    const int ilo = wid * 16 + (lane >> 2);
    const int ihi = ilo + 8;
    const size_t rlo = (size_t)(b * N_ + tok[ilo]) * 1536 + h * 64 + (lane & 3) * 2;
    const size_t rhi = (size_t)(b * N_ + tok[ihi]) * 1536 + h * 64 + (lane & 3) * 2;
    #pragma unroll
    for (int ni = 0; ni < 8; ni++) {
        float o0 = accO[ni][0] * inv0, o1 = accO[ni][1] * inv0;
        float o2 = accO[ni][2] * inv1, o3 = accO[ni][3] * inv1;
        __nv_bfloat16 h0, q0, h1, q1, h2, q2, h3, q3;
        bsplit(o0, h0, q0); bsplit(o1, h1, q1);
        bsplit(o2, h2, q2); bsplit(o3, h3, q3);
        __nv_bfloat162 hiA; hiA.x = h0; hiA.y = h1;
        __nv_bfloat162 loA; loA.x = q0; loA.y = q1;
        __nv_bfloat162 hiB; hiB.x = h2; hiB.y = h3;
        __nv_bfloat162 loB; loB.x = q2; loB.y = q3;
        *(__nv_bfloat162*)(g_o_ext + rlo + ni * 8)        = hiA;
        *(__nv_bfloat162*)(g_o_ext + rlo + ni * 8 + 512)  = hiA;
        *(__nv_bfloat162*)(g_o_ext + rlo + ni * 8 + 1024) = loA;
        *(__nv_bfloat162*)(g_o_ext + rhi + ni * 8)        = hiB;
        *(__nv_bfloat162*)(g_o_ext + rhi + ni * 8 + 512)  = hiB;
        *(__nv_bfloat162*)(g_o_ext + rhi + ni * 8 + 1024) = loB;
    }
}

__global__ void extras_kernel(float* __restrict__ outp, int write_rp) {
    int i = blockIdx.x * 256 + threadIdx.x;
    if (i < MT) {
        outp[MT * D_ + i] = (float)g_assigned[i];
        if (write_rp) outp[MT * D_ + MT + i] = g_rp[i];
    }
}

extern "C" void kernel_launch(void* const* d_in, const int* in_sizes, int n_in,
                              void* d_out, int out_size) {
    const float* x     = (const float*)d_in[0];
    const float* r_w   = (const float*)d_in[1];
    const float* r_b   = (const float*)d_in[2];
    const float* g1    = (const float*)d_in[3];
    const float* b1    = (const float*)d_in[4];
    const float* g2    = (const float*)d_in[5];
    const float* b2    = (const float*)d_in[6];
    const float* w_qkv = (const float*)d_in[7];
    const float* w_o   = (const float*)d_in[8];
    const float* b_o   = (const float*)d_in[9];
    const float* w1    = (const float*)d_in[10];
    const float* b1f   = (const float*)d_in[11];
    const float* w2    = (const float*)d_in[12];
    const float* b2f   = (const float*)d_in[13];
    const float* alpha = (const float*)d_in[14];
    float* out = (float*)d_out;

    static const int FATTN_SMEM = 2 * 64 * 400 + 2 * 64 * 144;
    cudaFuncSetAttribute(fattn_kernel, cudaFuncAttributeMaxDynamicSharedMemorySize, FATTN_SMEM);

    router_kernel<<<MT / 8, 256>>>(x, r_w, r_b);
    assign_kernel<<<B_, 1024>>>();
    zfill_kernel<<<MT, 256>>>();

    wconv_kernel<0><<<(512 * 1536 + 255) / 256, 256>>>(w_qkv, 512 * 1536);
    wconv_kernel<1><<<(512 * 512 + 255) / 256, 256>>>(w_o, 512 * 512);
    wconv_kernel<2><<<(512 * 2048 + 255) / 256, 256>>>(w1, 512 * 2048);
    wconv_kernel<3><<<(2048 * 512 + 255) / 256, 256>>>(w2, 2048 * 512);

    ln_kernel<0><<<MT, 256>>>(x, g1, b1);
    tgemm_kernel<0, 1536, 1536><<<dim3(12, 64), 256>>>(nullptr, nullptr);
    fattn_kernel<<<dim3(80, B_), 128, FATTN_SMEM>>>();
    tgemm_kernel<1, 1536, 512><<<dim3(4, 64), 256>>>(b_o, x);
    prepout_kernel<<<MT, 256>>>(out);
    ln_kernel<1><<<MT, 256>>>(x, g2, b2);
    ggemm_kernel<2><<<dim3(80, B_), 256>>>(b1f, nullptr, nullptr);
    ggemm_kernel<3><<<dim3(52, B_), 256>>>(b2f, alpha, out);
    reduce3_kernel<<<B_ * 512, 256>>>(b2f, alpha, out);

    if (out_size >= MT * D_ + MT) {
        int write_rp = (out_size >= MT * D_ + 2 * MT) ? 1 : 0;
        extras_kernel<<<(MT + 255) / 256, 256>>>(out, write_rp);
    }
}

// round 9
// speedup vs baseline: 5.4968x; 1.2259x over previous
#include <cuda_runtime.h>
#include <cuda_bf16.h>
#include <cstdint>
#include <math.h>

#define B_  4
#define N_  2048
#define D_  512
#define H_  8
#define E_  4
#define MT  (B_*N_)

__device__ float g_probs[MT*E_];
__device__ int   g_dtok[MT];
__device__ int   g_assigned[MT];
__device__ int   g_perm[MT];
__device__ float g_rp[MT];
__device__ float g_z [MT*D_];
__device__ float g_fpart[4][B_*512*512];
__device__ __nv_bfloat16 g_h_ext  [MT*1536];
__device__ __nv_bfloat16 g_o_ext  [MT*1536];
__device__ __nv_bfloat16 g_hm_ext [MT*1536];
__device__ __nv_bfloat16 g_hid_ext[(size_t)MT*6144];   // permuted rows
__device__ __nv_bfloat16 g_qext[(size_t)B_*H_*N_*192];
__device__ __nv_bfloat16 g_kext[(size_t)B_*H_*N_*192];
__device__ __nv_bfloat16 g_vh [(size_t)B_*H_*N_*64];
__device__ __nv_bfloat16 g_vl [(size_t)B_*H_*N_*64];
__device__ __nv_bfloat16 g_wqkv_ext[1536*1536];
__device__ __nv_bfloat16 g_wo_ext  [1536*512];
__device__ __nv_bfloat16 g_w1_ext  [1536*2048];
__device__ __nv_bfloat16 g_w2_ext  [6144*512];

__constant__ int c_head[80] = {
    0,0,0,0,0,0,0,0,0,0,0,0,0,0,0,0,0,0,0,0,0,0,0,0,0,0,0,0,0,0,0,0,
    1,1,1,1,1,1,1,1,1,1,1,1,1,1,1,1,
    2,2,2,2,2,2,2,2, 3,3,3,3,3,3,3,3,
    4,4,4,4, 5,5,5,5, 6,6,6,6, 7,7,7,7};
__constant__ int c_chunk[80] = {
    0,1,2,3,4,5,6,7,8,9,10,11,12,13,14,15,16,17,18,19,20,21,22,23,24,25,26,27,28,29,30,31,
    0,1,2,3,4,5,6,7,8,9,10,11,12,13,14,15,
    0,1,2,3,4,5,6,7, 0,1,2,3,4,5,6,7,
    0,1,2,3, 0,1,2,3, 0,1,2,3, 0,1,2,3};

__device__ __forceinline__ void bsplit(float v, __nv_bfloat16& h, __nv_bfloat16& l) {
    h = __float2bfloat16(v);
    l = __float2bfloat16(v - __bfloat162float(h));
}
__device__ __forceinline__ uint32_t packb(__nv_bfloat16 a, __nv_bfloat16 b) {
    __nv_bfloat162 t; t.x = a; t.y = b; return *(uint32_t*)&t;
}

__global__ void router_kernel(const float* __restrict__ x,
                              const float* __restrict__ rw,
                              const float* __restrict__ rb) {
    int warp = threadIdx.x >> 5, lane = threadIdx.x & 31;
    int t = blockIdx.x * 8 + warp;
    const float* xr = x + t * D_;
    double a0 = 0, a1 = 0, a2 = 0, a3 = 0;
    for (int j = lane; j < D_; j += 32) {
        double xv = (double)xr[j];
        const float* w = rw + j * E_;
        a0 += xv * (double)w[0]; a1 += xv * (double)w[1];
        a2 += xv * (double)w[2]; a3 += xv * (double)w[3];
    }
    #pragma unroll
    for (int o = 16; o > 0; o >>= 1) {
        a0 += __shfl_down_sync(0xffffffffu, a0, o);
        a1 += __shfl_down_sync(0xffffffffu, a1, o);
        a2 += __shfl_down_sync(0xffffffffu, a2, o);
        a3 += __shfl_down_sync(0xffffffffu, a3, o);
    }
    if (lane == 0) {
        double l0 = a0 + (double)rb[0], l1 = a1 + (double)rb[1];
        double l2 = a2 + (double)rb[2], l3 = a3 + (double)rb[3];
        double mx = fmax(fmax(l0, l1), fmax(l2, l3));
        double e0 = exp(l0 - mx), e1 = exp(l1 - mx), e2 = exp(l2 - mx), e3 = exp(l3 - mx);
        double s = e0 + e1 + e2 + e3;
        float* p = g_probs + t * 4;
        p[0] = (float)(e0 / s); p[1] = (float)(e1 / s);
        p[2] = (float)(e2 / s); p[3] = (float)(e3 / s);
    }
}

__device__ __forceinline__ unsigned int f2ord(float f) {
    unsigned int u = __float_as_uint(f);
    return (u & 0x80000000u) ? ~u : (u | 0x80000000u);
}

// 3 passes only: after e3/e2/e1 claim 1024 tokens, the remaining 1024 all land
// in e0 (cap 1024 >= remaining, and leftover rule is also e0) — pass 0 is a no-op.
__global__ __launch_bounds__(1024) void assign_kernel() {
    const int b = blockIdx.x, tid = threadIdx.x;
    __shared__ unsigned long long key[N_];
    __shared__ int sas[N_];
    __shared__ int cnt[4];
    sas[tid] = -1; sas[tid + 1024] = -1;
    if (tid < 4) cnt[tid] = 0;
    __syncthreads();
    const int capByE[4] = {1024, 512, 256, 256};
    for (int p = 0; p < 3; p++) {
        const int e = 3 - p, cap = capByE[e];
        #pragma unroll
        for (int ii = 0; ii < 2; ii++) {
            int i = tid + ii * 1024;
            float pr = (sas[i] < 0) ? g_probs[(b * N_ + i) * E_ + e] : -1.0f;
            key[i] = ((unsigned long long)f2ord(pr) << 32) | (unsigned int)(0xFFFFFFFFu - (unsigned)i);
        }
        __syncthreads();
        for (int k = 2; k <= N_; k <<= 1) {
            for (int j = k >> 1; j > 0; j >>= 1) {
                #pragma unroll
                for (int ii = 0; ii < 2; ii++) {
                    int i = tid + ii * 1024, ixj = i ^ j;
                    if (ixj > i) {
                        unsigned long long a = key[i], c = key[ixj];
                        bool sw = ((i & k) == 0) ? (a < c) : (a > c);
                        if (sw) { key[i] = c; key[ixj] = a; }
                    }
                }
                __syncthreads();
            }
        }
        #pragma unroll
        for (int ii = 0; ii < 2; ii++) {
            int pos = tid + ii * 1024;
            if (pos < cap) {
                unsigned long long kk = key[pos];
                if ((unsigned int)(kk >> 32) >= 0x80000000u)
                    sas[(int)(0xFFFFFFFFu - (unsigned int)(kk & 0xFFFFFFFFu))] = e;
            }
        }
        __syncthreads();
    }
    const int startE[4] = {1024, 512, 256, 0};
    #pragma unroll
    for (int ii = 0; ii < 2; ii++) {
        int i = tid + ii * 1024;
        int a = sas[i]; if (a < 0) a = 0;
        int gi = b * N_ + i;
        g_assigned[gi] = a;
        g_dtok[gi] = 64 << a;
        g_rp[gi] = g_probs[gi * E_ + a];
        int pos = startE[a] + atomicAdd(&cnt[a], 1);
        g_perm[b * N_ + pos] = i;
    }
}

// after z is final: masked cols of out = z (grouped FFN2 writes only unmasked)
__global__ void prepout_kernel(float* __restrict__ outp) {
    int m = blockIdx.x;
    int n = threadIdx.x * 2;
    if (n >= g_dtok[m]) {
        *(float2*)(outp + (size_t)m * 512 + n) = *(const float2*)(g_z + (size_t)m * 512 + n);
    }
}

template<int PASS>
__global__ __launch_bounds__(256) void ln_kernel(const float* __restrict__ xin,
                                                 const float* __restrict__ gam,
                                                 const float* __restrict__ bet) {
    const int t = blockIdx.x;
    const float* r = (PASS == 0 ? xin : g_z) + t * D_;
    const int tid = threadIdx.x, lane = tid & 31, wid = tid >> 5;
    __shared__ float red[8];
    __shared__ float s_mu, s_rstd;
    float x0 = r[tid], x1 = r[tid + 256];
    float s = x0 + x1;
    #pragma unroll
    for (int o = 16; o > 0; o >>= 1) s += __shfl_down_sync(0xffffffffu, s, o);
    if (lane == 0) red[wid] = s;
    __syncthreads();
    if (tid == 0) {
        float tt = 0;
        #pragma unroll
        for (int w = 0; w < 8; w++) tt += red[w];
        s_mu = tt * (1.0f / 512.0f);
    }
    __syncthreads();
    float mu = s_mu;
    float d0 = x0 - mu, d1 = x1 - mu;
    float q = d0 * d0 + d1 * d1;
    #pragma unroll
    for (int o = 16; o > 0; o >>= 1) q += __shfl_down_sync(0xffffffffu, q, o);
    if (lane == 0) red[wid] = q;
    __syncthreads();
    if (tid == 0) {
        float tt = 0;
        #pragma unroll
        for (int w = 0; w < 8; w++) tt += red[w];
        s_rstd = rsqrtf(tt * (1.0f / 512.0f) + 1e-5f);
    }
    __syncthreads();
    float rstd = s_rstd;
    int dt = g_dtok[t];
    float y0 = (tid < dt)       ? (d0 * rstd * gam[tid]       + bet[tid])       : 0.0f;
    float y1 = (tid + 256 < dt) ? (d1 * rstd * gam[tid + 256] + bet[tid + 256]) : 0.0f;
    __nv_bfloat16 h0, l0, h1, l1;
    bsplit(y0, h0, l0); bsplit(y1, h1, l1);
    __nv_bfloat16* e = (PASS == 0 ? g_h_ext : g_hm_ext) + (size_t)t * 1536;
    e[tid]        = h0; e[tid + 512]        = h0; e[tid + 1024]        = l0;
    e[tid + 256]  = h1; e[tid + 256 + 512]  = h1; e[tid + 256 + 1024]  = l1;
}

// fused weight conversion: all 4 weights in one launch
__global__ void wconv_all_kernel(const float* __restrict__ wqkv,
                                 const float* __restrict__ wo,
                                 const float* __restrict__ w1,
                                 const float* __restrict__ w2) {
    int i = blockIdx.x * 256 + threadIdx.x;
    const float* src; __nv_bfloat16* ext; int total, off;
    if (i < 786432)       { src = wqkv; ext = g_wqkv_ext; total = 786432;  off = i; }
    else if (i < 1048576) { src = wo;   ext = g_wo_ext;   total = 262144;  off = i - 786432; }
    else if (i < 2097152) { src = w1;   ext = g_w1_ext;   total = 1048576; off = i - 1048576; }
    else                  { src = w2;   ext = g_w2_ext;   total = 1048576; off = i - 2097152; }
    __nv_bfloat16 h, l;
    bsplit(src[off], h, l);
    ext[off] = h; ext[total + off] = l; ext[2 * total + off] = h;
}

__device__ __forceinline__ void mma16816(float* c, const uint32_t* a, const uint32_t* b) {
    asm volatile("mma.sync.aligned.m16n8k16.row.col.f32.bf16.bf16.f32 "
                 "{%0,%1,%2,%3},{%4,%5,%6,%7},{%8,%9},{%0,%1,%2,%3};"
                 : "+f"(c[0]), "+f"(c[1]), "+f"(c[2]), "+f"(c[3])
                 : "r"(a[0]), "r"(a[1]), "r"(a[2]), "r"(a[3]), "r"(b[0]), "r"(b[1]));
}

// ---------------- K-restricted QKV / O-proj GEMM ----------------
// Rows gathered per (batch, expert segment) via perm; K = 3d (chunk map); N stays dense.
// Epilogue is R5's proven one with m -> sT[row], dt = 64<<e.
// blockIdx.y in [0,64): b = y>>4, seg = y&15: {0,1}->e3, {2,3}->e2, {4..7}->e1, {8..15}->e0.
template<int EPI, int NC>   // EPI 0: QKV (NC=1536); EPI 1: O-proj (NC=512)
__global__ void __launch_bounds__(256, 2) tgk_kernel(const float* __restrict__ bias,
                                                     const float* __restrict__ resid) {
    const __nv_bfloat16* Aext = (EPI == 0) ? g_h_ext : g_o_ext;
    const __nv_bfloat16* Bext = (EPI == 0) ? g_wqkv_ext : g_wo_ext;

    const int tid = threadIdx.x, lane = tid & 31, wid = tid >> 5;
    const int y = blockIdx.y;
    const int b = y >> 4, seg = y & 15;
    int e, mt;
    if (seg < 2)      { e = 3; mt = seg; }
    else if (seg < 4) { e = 2; mt = seg - 2; }
    else if (seg < 8) { e = 1; mt = seg - 4; }
    else              { e = 0; mt = seg - 8; }
    const int d = 64 << e;
    const int ld = 6 + e;
    const int dm = d - 1;
    const int NS = (3 * d) >> 5;
    const int segstart = (e == 3) ? 0 : (e == 2) ? 256 : (e == 1) ? 512 : 1024;
    const int bn = blockIdx.x * 128;

    __shared__ __align__(16) unsigned char smA[2][128 * 64];
    __shared__ __align__(16) unsigned char smB[2][32 * 256];
    __shared__ int sT[128];
    if (tid < 128) sT[tid] = g_perm[b * 2048 + segstart + mt * 128 + tid];
    __syncthreads();

    const int rA0 = tid >> 2, cA = tid & 3, rA1 = rA0 + 64;
    const __nv_bfloat16* Ap0 = Aext + (size_t)(b * 2048 + sT[rA0]) * 1536 + cA * 8;
    const __nv_bfloat16* Ap1 = Aext + (size_t)(b * 2048 + sT[rA1]) * 1536 + cA * 8;
    const int oA0 = rA0 * 64 + ((cA ^ ((rA0 >> 1) & 3)) << 4);
    const int oA1 = rA1 * 64 + ((cA ^ ((rA1 >> 1) & 3)) << 4);
    const int rB0 = tid >> 4, cB = tid & 15, rB1 = rB0 + 16;
    const __nv_bfloat16* Bp0 = Bext + (size_t)rB0 * NC + bn + cB * 8;
    const __nv_bfloat16* Bp1 = Bext + (size_t)rB1 * NC + bn + cB * 8;
    const int oB0 = rB0 * 256 + ((cB ^ (rB0 & 7)) << 4);
    const int oB1 = rB1 * 256 + ((cB ^ (rB1 & 7)) << 4);

    const int wm = (wid >> 2) * 64;
    const int widn = wid & 3;

    float acc[4][4][4];
    #pragma unroll
    for (int i = 0; i < 4; i++)
        #pragma unroll
        for (int j = 0; j < 4; j++)
            #pragma unroll
            for (int k = 0; k < 4; k++) acc[i][j][k] = 0.0f;

    // per-slab global-K base: chunk*512 + (k mod d). Slabs (32 wide) never straddle chunks.
    #define KSTAGE(buf, slab) { \
        int k0_ = (slab) * 32; int kb_ = ((k0_ >> ld) << 9) + (k0_ & dm); \
        uint32_t ba_ = (uint32_t)__cvta_generic_to_shared(smA[buf]); \
        uint32_t bb_ = (uint32_t)__cvta_generic_to_shared(smB[buf]); \
        asm volatile("cp.async.cg.shared.global [%0],[%1],16;\n" :: "r"(ba_ + oA0), "l"(Ap0 + kb_)); \
        asm volatile("cp.async.cg.shared.global [%0],[%1],16;\n" :: "r"(ba_ + oA1), "l"(Ap1 + kb_)); \
        asm volatile("cp.async.cg.shared.global [%0],[%1],16;\n" :: "r"(bb_ + oB0), "l"(Bp0 + (size_t)kb_ * NC)); \
        asm volatile("cp.async.cg.shared.global [%0],[%1],16;\n" :: "r"(bb_ + oB1), "l"(Bp1 + (size_t)kb_ * NC)); \
        asm volatile("cp.async.commit_group;\n"); }

    KSTAGE(0, 0);

    #pragma unroll 1
    for (int s = 0; s < NS; s++) {
        int cur = s & 1;
        if (s + 1 < NS) {
            KSTAGE(cur ^ 1, s + 1);
            asm volatile("cp.async.wait_group 1;\n");
        } else {
            asm volatile("cp.async.wait_group 0;\n");
        }
        __syncthreads();
        unsigned char* As = smA[cur];
        unsigned char* Bs = smB[cur];
        #pragma unroll
        for (int kk = 0; kk < 2; kk++) {
            uint32_t af[4][4], bfr[4][2];
            #pragma unroll
            for (int mi = 0; mi < 4; mi++) {
                int r = wm + mi * 16 + (lane & 7) + ((lane & 8) ? 8 : 0);
                int c = kk * 2 + ((lane & 16) ? 1 : 0);
                uint32_t sa = (uint32_t)__cvta_generic_to_shared(
                    As + r * 64 + ((c ^ ((r >> 1) & 3)) << 4));
                asm volatile("ldmatrix.sync.aligned.m8n8.x4.shared.b16 {%0,%1,%2,%3},[%4];"
                             : "=r"(af[mi][0]), "=r"(af[mi][1]), "=r"(af[mi][2]), "=r"(af[mi][3])
                             : "r"(sa));
            }
            #pragma unroll
            for (int np = 0; np < 2; np++) {
                int kr = kk * 16 + (lane & 7) + ((lane & 8) ? 8 : 0);
                int c = widn * 4 + np * 2 + ((lane & 16) ? 1 : 0);
                uint32_t sb = (uint32_t)__cvta_generic_to_shared(
                    Bs + kr * 256 + ((c ^ (kr & 7)) << 4));
                asm volatile("ldmatrix.sync.aligned.m8n8.x4.trans.shared.b16 {%0,%1,%2,%3},[%4];"
                             : "=r"(bfr[np * 2][0]), "=r"(bfr[np * 2][1]),
                               "=r"(bfr[np * 2 + 1][0]), "=r"(bfr[np * 2 + 1][1])
                             : "r"(sb));
            }
            #pragma unroll
            for (int mi = 0; mi < 4; mi++)
                #pragma unroll
                for (int ni = 0; ni < 4; ni++)
                    mma16816(acc[mi][ni], af[mi], bfr[ni]);
        }
        __syncthreads();
    }

    const int l4 = lane >> 2, l2 = (lane & 3) * 2;
    const int dt = d;
    #pragma unroll
    for (int mi = 0; mi < 4; mi++) {
        #pragma unroll
        for (int hh = 0; hh < 2; hh++) {
            int mrl = wm + mi * 16 + l4 + hh * 8;
            int tokv = sT[mrl];
            #pragma unroll
            for (int ni = 0; ni < 4; ni++) {
                int n = bn + widn * 32 + ni * 8 + l2;
                float v0 = acc[mi][ni][hh * 2 + 0];
                float v1 = acc[mi][ni][hh * 2 + 1];
                if (EPI == 0) {
                    int chunk = n >> 9, f = n & 511;
                    int head = f >> 6, dd = f & 63;
                    bool on = (f < dt);
                    float w0 = on ? v0 : 0.0f;
                    float w1 = on ? v1 : 0.0f;
                    __nv_bfloat16 hh0, ll0, hh1, ll1;
                    bsplit(w0, hh0, ll0); bsplit(w1, hh1, ll1);
                    __nv_bfloat162 hi2; hi2.x = hh0; hi2.y = hh1;
                    __nv_bfloat162 lo2; lo2.x = ll0; lo2.y = ll1;
                    size_t base = (size_t)((b * H_ + head) * N_ + tokv);
                    if (chunk == 0) {
                        __nv_bfloat16* p = g_qext + base * 192 + dd;
                        *(__nv_bfloat162*)(p)       = hi2;
                        *(__nv_bfloat162*)(p + 64)  = hi2;
                        *(__nv_bfloat162*)(p + 128) = lo2;
                    } else if (chunk == 1) {
                        __nv_bfloat16* p = g_kext + base * 192 + dd;
                        *(__nv_bfloat162*)(p)       = hi2;
                        *(__nv_bfloat162*)(p + 64)  = lo2;
                        *(__nv_bfloat162*)(p + 128) = hi2;
                    } else {
                        *(__nv_bfloat162*)(g_vh + base * 64 + dd) = hi2;
                        *(__nv_bfloat162*)(g_vl + base * 64 + dd) = lo2;
                    }
                } else {
                    size_t row = (size_t)(b * 2048 + tokv) * 512;
                    float w0 = v0 + bias[n];
                    float w1 = v1 + bias[n + 1];
                    if (n >= dt) w0 = 0.0f;
                    if (n + 1 >= dt) w1 = 0.0f;
                    const float2 xr = *(const float2*)(resid + row + n);
                    float2 o; o.x = xr.x + w0; o.y = xr.y + w1;
                    *(float2*)(g_z + row + n) = o;
                }
            }
        }
    }
    #undef KSTAGE
}

// ---------------- grouped FFN GEMMs (proven in R8) ----------------
template<int EPI>
__global__ void __launch_bounds__(256, 2) ggemm_kernel(const float* __restrict__ bias,
                                                       const float* __restrict__ alpha,
                                                       float* __restrict__ outp) {
    const __nv_bfloat16* Aext = (EPI == 2) ? g_hm_ext : g_hid_ext;
    const __nv_bfloat16* Bext = (EPI == 2) ? g_w1_ext : g_w2_ext;
    constexpr int NC  = (EPI == 2) ? 2048 : 512;
    constexpr int SEG = (EPI == 3) ? 2048 : 512;
    constexpr size_t AROW = 3 * SEG;
    constexpr int TN0v = (EPI == 2) ? 2 : 1;
    constexpr int TN1v = (EPI == 2) ? 4 : 1;
    constexpr int TN2v = (EPI == 2) ? 8 : 2;
    constexpr int TN3v = (EPI == 2) ? 16 : 4;
    constexpr int TS3v = (EPI == 3) ? 4 : 1;
    constexpr int TS2v = (EPI == 3) ? 2 : 1;
    constexpr int C3 = 2 * TN3v * TS3v, C2 = 2 * TN2v * TS2v, C1 = 4 * TN1v;

    const int tid = threadIdx.x, lane = tid & 31, wid = tid >> 5;
    const int b = blockIdx.y;
    int idx = blockIdx.x;
    int e, loc, TN, TS;
    if (idx < C3)                 { e = 3; loc = idx;                  TN = TN3v; TS = TS3v; }
    else if (idx < C3 + C2)       { e = 2; loc = idx - C3;             TN = TN2v; TS = TS2v; }
    else if (idx < C3 + C2 + C1)  { e = 1; loc = idx - (C3 + C2);      TN = TN1v; TS = 1; }
    else                          { e = 0; loc = idx - (C3 + C2 + C1); TN = TN0v; TS = 1; }
    const int mt = loc / (TN * TS);
    int rem = loc - mt * (TN * TS);
    const int nt = rem / TS;
    const int sp = rem - nt * TS;
    const int d = 64 << e;
    const int ld = ((EPI == 3) ? 8 : 6) + e;
    const int dm = (1 << ld) - 1;
    const int NStot = (3 << ld) >> 5;
    const int per = NStot / TS;
    const int slab0 = sp * per, slab1 = slab0 + per;
    const int segstart = (e == 0) ? 1024 : (e == 1) ? 512 : (e == 2) ? 256 : 0;

    __shared__ __align__(16) unsigned char smA[2][128 * 64];
    __shared__ __align__(16) unsigned char smB[2][32 * 256];
    __shared__ int sA[128], sT[128];
    if (tid < 128) {
        int pos = segstart + mt * 128 + tid;
        int pv = g_perm[b * 2048 + pos];
        sT[tid] = pv;
        sA[tid] = (EPI == 3) ? (b * 2048 + pos) : (b * 2048 + pv);
    }
    __syncthreads();

    const int rA0 = tid >> 2, cA = tid & 3, rA1 = rA0 + 64;
    const __nv_bfloat16* Ap0 = Aext + (size_t)sA[rA0] * AROW + cA * 8;
    const __nv_bfloat16* Ap1 = Aext + (size_t)sA[rA1] * AROW + cA * 8;
    const int oA0 = rA0 * 64 + ((cA ^ ((rA0 >> 1) & 3)) << 4);
    const int oA1 = rA1 * 64 + ((cA ^ ((rA1 >> 1) & 3)) << 4);
    const int rB0 = tid >> 4, cB = tid & 15, rB1 = rB0 + 16;
    const int bc = nt * 128 + cB * 8;
    const __nv_bfloat16* Bp0 = Bext + (size_t)rB0 * NC + bc;
    const __nv_bfloat16* Bp1 = Bext + (size_t)rB1 * NC + bc;
    const int oB0 = rB0 * 256 + ((cB ^ (rB0 & 7)) << 4);
    const int oB1 = rB1 * 256 + ((cB ^ (rB1 & 7)) << 4);

    const int wm = (wid >> 2) * 64;
    const int widn = wid & 3;

    float acc[4][4][4];
    #pragma unroll
    for (int i = 0; i < 4; i++)
        #pragma unroll
        for (int jx = 0; jx < 4; jx++)
            #pragma unroll
            for (int k = 0; k < 4; k++) acc[i][jx][k] = 0.0f;

    #define GSTAGE(buf, slab) { \
        int kk_ = (slab) * 32; int kb_ = ((kk_ >> ld) * SEG) + (kk_ & dm); \
        uint32_t ba_ = (uint32_t)__cvta_generic_to_shared(smA[buf]); \
        uint32_t bb_ = (uint32_t)__cvta_generic_to_shared(smB[buf]); \
        asm volatile("cp.async.cg.shared.global [%0],[%1],16;\n" :: "r"(ba_ + oA0), "l"(Ap0 + kb_)); \
        asm volatile("cp.async.cg.shared.global [%0],[%1],16;\n" :: "r"(ba_ + oA1), "l"(Ap1 + kb_)); \
        asm volatile("cp.async.cg.shared.global [%0],[%1],16;\n" :: "r"(bb_ + oB0), "l"(Bp0 + (size_t)kb_ * NC)); \
        asm volatile("cp.async.cg.shared.global [%0],[%1],16;\n" :: "r"(bb_ + oB1), "l"(Bp1 + (size_t)kb_ * NC)); \
        asm volatile("cp.async.commit_group;\n"); }

    GSTAGE(0, slab0);

    #pragma unroll 1
    for (int s = slab0; s < slab1; s++) {
        int cur = (s - slab0) & 1;
        if (s + 1 < slab1) {
            GSTAGE(cur ^ 1, s + 1);
            asm volatile("cp.async.wait_group 1;\n");
        } else {
            asm volatile("cp.async.wait_group 0;\n");
        }
        __syncthreads();
        unsigned char* As = smA[cur];
        unsigned char* Bs = smB[cur];
        #pragma unroll
        for (int kk = 0; kk < 2; kk++) {
            uint32_t af[4][4], bfr[4][2];
            #pragma unroll
            for (int mi = 0; mi < 4; mi++) {
                int r = wm + mi * 16 + (lane & 7) + ((lane & 8) ? 8 : 0);
                int c = kk * 2 + ((lane & 16) ? 1 : 0);
                uint32_t sa = (uint32_t)__cvta_generic_to_shared(
                    As + r * 64 + ((c ^ ((r >> 1) & 3)) << 4));
                asm volatile("ldmatrix.sync.aligned.m8n8.x4.shared.b16 {%0,%1,%2,%3},[%4];"
                             : "=r"(af[mi][0]), "=r"(af[mi][1]), "=r"(af[mi][2]), "=r"(af[mi][3])
                             : "r"(sa));
            }
            #pragma unroll
            for (int np = 0; np < 2; np++) {
                int kr = kk * 16 + (lane & 7) + ((lane & 8) ? 8 : 0);
                int c = widn * 4 + np * 2 + ((lane & 16) ? 1 : 0);
                uint32_t sb = (uint32_t)__cvta_generic_to_shared(
                    Bs + kr * 256 + ((c ^ (kr & 7)) << 4));
                asm volatile("ldmatrix.sync.aligned.m8n8.x4.trans.shared.b16 {%0,%1,%2,%3},[%4];"
                             : "=r"(bfr[np * 2][0]), "=r"(bfr[np * 2][1]),
                               "=r"(bfr[np * 2 + 1][0]), "=r"(bfr[np * 2 + 1][1])
                             : "r"(sb));
            }
            #pragma unroll
            for (int mi = 0; mi < 4; mi++)
                #pragma unroll
                for (int ni = 0; ni < 4; ni++)
                    mma16816(acc[mi][ni], af[mi], bfr[ni]);
        }
        __syncthreads();
    }

    const int l4 = lane >> 2, l2 = (lane & 3) * 2;

    if (EPI == 3 && TS > 1) {
        #pragma unroll
        for (int mi = 0; mi < 4; mi++) {
            #pragma unroll
            for (int hh = 0; hh < 2; hh++) {
                int mrl = wm + mi * 16 + l4 + hh * 8;
                int pos = segstart + mt * 128 + mrl;
                #pragma unroll
                for (int ni = 0; ni < 4; ni++) {
                    int n = nt * 128 + widn * 32 + ni * 8 + l2;
                    float2 v; v.x = acc[mi][ni][hh * 2]; v.y = acc[mi][ni][hh * 2 + 1];
                    *(float2*)&g_fpart[sp][((b << 9) + pos) * 512 + n] = v;
                }
            }
        }
        return;
    }

    float aval = 0.0f;
    if (EPI == 3) aval = alpha[0];

    #pragma unroll
    for (int mi = 0; mi < 4; mi++) {
        #pragma unroll
        for (int hh = 0; hh < 2; hh++) {
            int mrl = wm + mi * 16 + l4 + hh * 8;
            int tok = sT[mrl];
            #pragma unroll
            for (int ni = 0; ni < 4; ni++) {
                int n = nt * 128 + widn * 32 + ni * 8 + l2;
                float v0 = acc[mi][ni][hh * 2 + 0];
                float v1 = acc[mi][ni][hh * 2 + 1];
                if (EPI == 2) {
                    if (n < 4 * d) {
                        int pos = segstart + mt * 128 + mrl;
                        size_t row = (size_t)(b * 2048 + pos) * 6144;
                        float w = v0 + bias[n];
                        float c1 = 0.7978845608028654f * (w + 0.044715f * w * w * w);
                        float h0 = 0.5f * w * (1.0f + tanhf(c1));
                        w = v1 + bias[n + 1];
                        c1 = 0.7978845608028654f * (w + 0.044715f * w * w * w);
                        float h1 = 0.5f * w * (1.0f + tanhf(c1));
                        __nv_bfloat16 a0, b0, a1, b1;
                        bsplit(h0, a0, b0); bsplit(h1, a1, b1);
                        __nv_bfloat162 hi; hi.x = a0; hi.y = a1;
                        __nv_bfloat162 lo; lo.x = b0; lo.y = b1;
                        *(__nv_bfloat162*)(g_hid_ext + row + n)        = hi;
                        *(__nv_bfloat162*)(g_hid_ext + row + n + 2048) = hi;
                        *(__nv_bfloat162*)(g_hid_ext + row + n + 4096) = lo;
                    }
                } else {
                    if (n < d) {
                        size_t row = (size_t)(b * 2048 + tok) * 512;
                        float gm = aval * g_rp[b * 2048 + tok] + 1.0f;
                        float w0 = v0 + bias[n];
                        float w1 = v1 + bias[n + 1];
                        const float2 zz = *(const float2*)(g_z + row + n);
                        float2 o; o.x = zz.x + gm * w0; o.y = zz.y + gm * w1;
                        *(float2*)(outp + row + n) = o;
                    }
                }
            }
        }
    }
    #undef GSTAGE
}

__global__ void reduce3_kernel(const float* __restrict__ b2f,
                               const float* __restrict__ alpha,
                               float* __restrict__ outp) {
    int rowid = blockIdx.x;
    int b = rowid >> 9, pos = rowid & 511;
    int ns = (pos < 256) ? 4 : 2;
    int d = (pos < 256) ? 512 : 256;
    int tok = g_perm[b * 2048 + pos];
    float gm = alpha[0] * g_rp[b * 2048 + tok] + 1.0f;
    size_t row = (size_t)(b * 2048 + tok) * 512;
    int base = ((b << 9) + pos) * 512;
    for (int n = threadIdx.x; n < d; n += 256) {
        float s = g_fpart[0][base + n] + g_fpart[1][base + n];
        if (ns == 4) s += g_fpart[2][base + n] + g_fpart[3][base + n];
        s += b2f[n];
        outp[row + n] = g_z[row + n] + gm * s;
    }
}

// ---------------- tensor-core flash attention (proven) ----------------
__global__ void __launch_bounds__(128, 3) fattn_kernel() {
    const int b = blockIdx.y;
    const int slot = blockIdx.x;
    const int h = c_head[slot];
    const int ch = c_chunk[slot];
    extern __shared__ __align__(16) unsigned char sm[];
    unsigned char* Qs  = sm;
    unsigned char* Ks  = sm + 64 * 400;
    unsigned char* Vhs = sm + 2 * 64 * 400;
    unsigned char* Vls = Vhs + 64 * 144;
    __shared__ int tok[64];
    const int tid = threadIdx.x, lane = tid & 31, wid = tid >> 5;

    if (tid < 64) tok[tid] = g_perm[b * N_ + ch * 64 + tid];
    __syncthreads();
    const size_t bh = (size_t)(b * H_ + h) * N_;

    for (int i = tid; i < 64 * 24; i += 128) {
        int r = i / 24, c = i % 24;
        const __nv_bfloat16* g = g_qext + (bh + tok[r]) * 192 + c * 8;
        uint32_t s = (uint32_t)__cvta_generic_to_shared(Qs + r * 400 + c * 16);
        asm volatile("cp.async.cg.shared.global [%0],[%1],16;\n" :: "r"(s), "l"(g));
    }
    asm volatile("cp.async.commit_group;\ncp.async.wait_group 0;\n");
    __syncthreads();

    float accO[8][4];
    #pragma unroll
    for (int i = 0; i < 8; i++)
        #pragma unroll
        for (int j = 0; j < 4; j++) accO[i][j] = 0.0f;
    float m0 = -3.0e38f, m1 = -3.0e38f, l0 = 0.0f, l1 = 0.0f;

    for (int k0 = 0; k0 < N_; k0 += 64) {
        for (int i = tid; i < 64 * 24; i += 128) {
            int r = i / 24, c = i % 24;
            const __nv_bfloat16* g = g_kext + (bh + k0 + r) * 192 + c * 8;
            uint32_t s = (uint32_t)__cvta_generic_to_shared(Ks + r * 400 + c * 16);
            asm volatile("cp.async.cg.shared.global [%0],[%1],16;\n" :: "r"(s), "l"(g));
        }
        for (int i = tid; i < 64 * 8; i += 128) {
            int r = i / 8, c = i % 8;
            const __nv_bfloat16* gh = g_vh + (bh + k0 + r) * 64 + c * 8;
            const __nv_bfloat16* gl = g_vl + (bh + k0 + r) * 64 + c * 8;
            uint32_t sh = (uint32_t)__cvta_generic_to_shared(Vhs + r * 144 + c * 16);
            uint32_t sl = (uint32_t)__cvta_generic_to_shared(Vls + r * 144 + c * 16);
            asm volatile("cp.async.cg.shared.global [%0],[%1],16;\n" :: "r"(sh), "l"(gh));
            asm volatile("cp.async.cg.shared.global [%0],[%1],16;\n" :: "r"(sl), "l"(gl));
        }
        asm volatile("cp.async.commit_group;\ncp.async.wait_group 0;\n");
        __syncthreads();

        float S[8][4];
        #pragma unroll
        for (int i = 0; i < 8; i++)
            #pragma unroll
            for (int j = 0; j < 4; j++) S[i][j] = 0.0f;

        const int qrow = wid * 16 + (lane & 15);
        const int krow7 = (lane & 7) + ((lane & 16) ? 8 : 0);
        const int kcsel = ((lane & 8) ? 1 : 0);
        #pragma unroll
        for (int ks = 0; ks < 12; ks++) {
            uint32_t qf[4];
            uint32_t sa = (uint32_t)__cvta_generic_to_shared(
                Qs + qrow * 400 + (ks * 2 + (lane >> 4)) * 16);
            asm volatile("ldmatrix.sync.aligned.m8n8.x4.shared.b16 {%0,%1,%2,%3},[%4];"
                         : "=r"(qf[0]), "=r"(qf[1]), "=r"(qf[2]), "=r"(qf[3]) : "r"(sa));
            #pragma unroll
            for (int p = 0; p < 4; p++) {
                uint32_t kf[4];
                uint32_t sb = (uint32_t)__cvta_generic_to_shared(
                    Ks + (p * 16 + krow7) * 400 + (ks * 2 + kcsel) * 16);
                asm volatile("ldmatrix.sync.aligned.m8n8.x4.shared.b16 {%0,%1,%2,%3},[%4];"
                             : "=r"(kf[0]), "=r"(kf[1]), "=r"(kf[2]), "=r"(kf[3]) : "r"(sb));
                mma16816(S[2 * p],     qf, kf);
                mma16816(S[2 * p + 1], qf, kf + 2);
            }
        }

        float mx0 = -3.0e38f, mx1 = -3.0e38f;
        #pragma unroll
        for (int ni = 0; ni < 8; ni++) {
            S[ni][0] *= 0.125f; S[ni][1] *= 0.125f; S[ni][2] *= 0.125f; S[ni][3] *= 0.125f;
            mx0 = fmaxf(mx0, fmaxf(S[ni][0], S[ni][1]));
            mx1 = fmaxf(mx1, fmaxf(S[ni][2], S[ni][3]));
        }
        mx0 = fmaxf(mx0, __shfl_xor_sync(0xffffffffu, mx0, 1));
        mx0 = fmaxf(mx0, __shfl_xor_sync(0xffffffffu, mx0, 2));
        mx1 = fmaxf(mx1, __shfl_xor_sync(0xffffffffu, mx1, 1));
        mx1 = fmaxf(mx1, __shfl_xor_sync(0xffffffffu, mx1, 2));
        float mn0 = fmaxf(m0, mx0), mn1 = fmaxf(m1, mx1);
        float cr0 = __expf(m0 - mn0), cr1 = __expf(m1 - mn1);
        float s0 = 0.0f, s1 = 0.0f;
        uint32_t pha[8], phb[8], pla[8], plb[8];
        #pragma unroll
        for (int ni = 0; ni < 8; ni++) {
            float p00 = __expf(S[ni][0] - mn0), p01 = __expf(S[ni][1] - mn0);
            float p10 = __expf(S[ni][2] - mn1), p11 = __expf(S[ni][3] - mn1);
            s0 += p00 + p01; s1 += p10 + p11;
            __nv_bfloat16 h00, l00, h01, l01, h10, l10, h11, l11;
            bsplit(p00, h00, l00); bsplit(p01, h01, l01);
            bsplit(p10, h10, l10); bsplit(p11, h11, l11);
            pha[ni] = packb(h00, h01); phb[ni] = packb(h10, h11);
            pla[ni] = packb(l00, l01); plb[ni] = packb(l10, l11);
        }
        s0 += __shfl_xor_sync(0xffffffffu, s0, 1);
        s0 += __shfl_xor_sync(0xffffffffu, s0, 2);
        s1 += __shfl_xor_sync(0xffffffffu, s1, 1);
        s1 += __shfl_xor_sync(0xffffffffu, s1, 2);
        l0 = l0 * cr0 + s0; l1 = l1 * cr1 + s1;
        m0 = mn0; m1 = mn1;
        #pragma unroll
        for (int ni = 0; ni < 8; ni++) {
            accO[ni][0] *= cr0; accO[ni][1] *= cr0;
            accO[ni][2] *= cr1; accO[ni][3] *= cr1;
        }

        const int vrow7 = (lane & 7) + ((lane & 8) ? 8 : 0);
        const int vcsel = ((lane & 16) ? 1 : 0);
        #pragma unroll
        for (int kt = 0; kt < 4; kt++) {
            uint32_t pa[4] = {pha[2 * kt], phb[2 * kt], pha[2 * kt + 1], phb[2 * kt + 1]};
            uint32_t la[4] = {pla[2 * kt], plb[2 * kt], pla[2 * kt + 1], plb[2 * kt + 1]};
            #pragma unroll
            for (int p = 0; p < 4; p++) {
                uint32_t vh[4], vl[4];
                uint32_t svh = (uint32_t)__cvta_generic_to_shared(
                    Vhs + (kt * 16 + vrow7) * 144 + (p * 2 + vcsel) * 16);
                uint32_t svl = (uint32_t)__cvta_generic_to_shared(
                    Vls + (kt * 16 + vrow7) * 144 + (p * 2 + vcsel) * 16);
                asm volatile("ldmatrix.sync.aligned.m8n8.x4.trans.shared.b16 {%0,%1,%2,%3},[%4];"
                             : "=r"(vh[0]), "=r"(vh[1]), "=r"(vh[2]), "=r"(vh[3]) : "r"(svh));
                asm volatile("ldmatrix.sync.aligned.m8n8.x4.trans.shared.b16 {%0,%1,%2,%3},[%4];"
                             : "=r"(vl[0]), "=r"(vl[1]), "=r"(vl[2]), "=r"(vl[3]) : "r"(svl));
                mma16816(accO[2 * p],     pa, vh);
                mma16816(accO[2 * p + 1], pa, vh + 2);
                mma16816(accO[2 * p],     pa, vl);
                mma16816(accO[2 * p + 1], pa, vl + 2);
                mma16816(accO[2 * p],     la, vh);
                mma16816(accO[2 * p + 1], la, vh + 2);
            }
        }
        __syncthreads();
    }

    float inv0 = 1.0f / l0, inv1 = 1.0f / l1;
    const int ilo = wid * 16 + (lane >> 2);
    const int ihi = ilo + 8;
    const size_t rlo = (size_t)(b * N_ + tok[ilo]) * 1536 + h * 64 + (lane & 3) * 2;
    const size_t rhi = (size_t)(b * N_ + tok[ihi]) * 1536 + h * 64 + (lane & 3) * 2;
    #pragma unroll
    for (int ni = 0; ni < 8; ni++) {
        float o0 = accO[ni][0] * inv0, o1 = accO[ni][1] * inv0;
        float o2 = accO[ni][2] * inv1, o3 = accO[ni][3] * inv1;
        __nv_bfloat16 h0, q0, h1, q1, h2, q2, h3, q3;
        bsplit(o0, h0, q0); bsplit(o1, h1, q1);
        bsplit(o2, h2, q2); bsplit(o3, h3, q3);
        __nv_bfloat162 hiA; hiA.x = h0; hiA.y = h1;
        __nv_bfloat162 loA; loA.x = q0; loA.y = q1;
        __nv_bfloat162 hiB; hiB.x = h2; hiB.y = h3;
        __nv_bfloat162 loB; loB.x = q2; loB.y = q3;
        *(__nv_bfloat162*)(g_o_ext + rlo + ni * 8)        = hiA;
        *(__nv_bfloat162*)(g_o_ext + rlo + ni * 8 + 512)  = hiA;
        *(__nv_bfloat162*)(g_o_ext + rlo + ni * 8 + 1024) = loA;
        *(__nv_bfloat162*)(g_o_ext + rhi + ni * 8)        = hiB;
        *(__nv_bfloat162*)(g_o_ext + rhi + ni * 8 + 512)  = hiB;
        *(__nv_bfloat162*)(g_o_ext + rhi + ni * 8 + 1024) = loB;
    }
}

__global__ void extras_kernel(float* __restrict__ outp, int write_rp) {
    int i = blockIdx.x * 256 + threadIdx.x;
    if (i < MT) {
        outp[MT * D_ + i] = (float)g_assigned[i];
        if (write_rp) outp[MT * D_ + MT + i] = g_rp[i];
    }
}

extern "C" void kernel_launch(void* const* d_in, const int* in_sizes, int n_in,
                              void* d_out, int out_size) {
    const float* x     = (const float*)d_in[0];
    const float* r_w   = (const float*)d_in[1];
    const float* r_b   = (const float*)d_in[2];
    const float* g1    = (const float*)d_in[3];
    const float* b1    = (const float*)d_in[4];
    const float* g2    = (const float*)d_in[5];
    const float* b2    = (const float*)d_in[6];
    const float* w_qkv = (const float*)d_in[7];
    const float* w_o   = (const float*)d_in[8];
    const float* b_o   = (const float*)d_in[9];
    const float* w1    = (const float*)d_in[10];
    const float* b1f   = (const float*)d_in[11];
    const float* w2    = (const float*)d_in[12];
    const float* b2f   = (const float*)d_in[13];
    const float* alpha = (const float*)d_in[14];
    float* out = (float*)d_out;

    static const int FATTN_SMEM = 2 * 64 * 400 + 2 * 64 * 144;
    cudaFuncSetAttribute(fattn_kernel, cudaFuncAttributeMaxDynamicSharedMemorySize, FATTN_SMEM);

    router_kernel<<<MT / 8, 256>>>(x, r_w, r_b);
    assign_kernel<<<B_, 1024>>>();
    wconv_all_kernel<<<3145728 / 256, 256>>>(w_qkv, w_o, w1, w2);

    ln_kernel<0><<<MT, 256>>>(x, g1, b1);
    tgk_kernel<0, 1536><<<dim3(12, 64), 256>>>(nullptr, nullptr);
    fattn_kernel<<<dim3(80, B_), 128, FATTN_SMEM>>>();
    tgk_kernel<1, 512><<<dim3(4, 64), 256>>>(b_o, x);
    prepout_kernel<<<MT, 256>>>(out);
    ln_kernel<1><<<MT, 256>>>(x, g2, b2);
    ggemm_kernel<2><<<dim3(80, B_), 256>>>(b1f, nullptr, nullptr);
    ggemm_kernel<3><<<dim3(52, B_), 256>>>(b2f, alpha, out);
    reduce3_kernel<<<B_ * 512, 256>>>(b2f, alpha, out);

    if (out_size >= MT * D_ + MT) {
        int write_rp = (out_size >= MT * D_ + 2 * MT) ? 1 : 0;
        extras_kernel<<<(MT + 255) / 256, 256>>>(out, write_rp);
    }
}